// round 8
// baseline (speedup 1.0000x reference)
#include <cuda_runtime.h>
#include <cuda_fp16.h>
#include <math.h>
#include <stdint.h>

#define NLR  50000
#define EMBD 128
#define ENUM 800000

#define AS_F 40    // padded A row stride (floats)
#define BS_F 36    // padded B^T row stride (floats)

// ---------------- device scratch (no allocations allowed) ----------------
__device__ float g_logits[(size_t)ENUM * 4];
__device__ float g_xl[(size_t)NLR * EMBD];
__device__ float g_xr[(size_t)NLR * EMBD];
__device__ float g_ln[(size_t)NLR * EMBD];
__device__ float g_h1[(size_t)NLR * EMBD];
__device__ float g_wT[128 * 768];           // wlT|wrT|weT|w1T(128x256)|w2T
__device__ int   g_cnt[NLR];
__device__ int   g_off[NLR + 1];
__device__ int   g_cur[NLR];
__device__ int   g_elist[ENUM];

#define WL_T 0
#define WR_T 16384
#define WE_T 32768
#define W1_T 49152
#define W2_T 81920

// ---------------- helpers ----------------
__device__ __forceinline__ uint32_t f2h2(float lo, float hi) {
    __half2 h = __floats2half2_rn(lo, hi);
    return *(uint32_t*)&h;
}
__device__ __forceinline__ uint32_t f2h2v(float2 v) { return f2h2(v.x, v.y); }

__device__ __forceinline__ void mma16(float c[4], const uint32_t a[4], const uint32_t b[2]) {
    asm volatile(
        "mma.sync.aligned.m16n8k16.row.col.f32.f16.f16.f32 "
        "{%0,%1,%2,%3},{%4,%5,%6,%7},{%8,%9},{%0,%1,%2,%3};\n"
        : "+f"(c[0]), "+f"(c[1]), "+f"(c[2]), "+f"(c[3])
        : "r"(a[0]), "r"(a[1]), "r"(a[2]), "r"(a[3]), "r"(b[0]), "r"(b[1]));
}

__device__ __forceinline__ void cp16(uint32_t saddr, const float* gptr, int sz) {
    asm volatile("cp.async.cg.shared.global [%0], [%1], 16, %2;\n"
                 :: "r"(saddr), "l"(gptr), "r"(sz));
}
__device__ __forceinline__ void cp_commit() { asm volatile("cp.async.commit_group;\n"); }
__device__ __forceinline__ void cp_wait1()  { asm volatile("cp.async.wait_group 1;\n"); }
__device__ __forceinline__ void cp_wait0()  { asm volatile("cp.async.wait_group 0;\n"); }
__device__ __forceinline__ uint32_t sa(const void* p) {
    return (uint32_t)__cvta_generic_to_shared(p);
}

#define AS_BYTES (2 * 128 * AS_F * 4)   // 40960
#define BS_BYTES (2 * 128 * BS_F * 4)   // 36864
#define SMEM_GEMM (AS_BYTES + BS_BYTES + 512)
#define SMEM_EDGE (AS_BYTES + BS_BYTES + 128 * 4 * 2 + 512)

// =================================================================
// one-time weight transpose: g_wT[n][k] = W[k][n] for 5 matrices
// =================================================================
__global__ void transpose5(const float* __restrict__ Wl, const float* __restrict__ Wr,
                           const float* __restrict__ We, const float* __restrict__ W1,
                           const float* __restrict__ W2) {
    __shared__ float t[32][33];
    int b = blockIdx.x;
    const float* W; float* out; int K;
    if      (b < 16) { W = Wl; out = g_wT + WL_T; K = 128; }
    else if (b < 32) { W = Wr; out = g_wT + WR_T; K = 128; b -= 16; }
    else if (b < 48) { W = We; out = g_wT + WE_T; K = 128; b -= 32; }
    else if (b < 80) { W = W1; out = g_wT + W1_T; K = 256; b -= 48; }
    else             { W = W2; out = g_wT + W2_T; K = 128; b -= 80; }
    const int ktiles = K >> 5;
    const int k0 = (b % ktiles) * 32, n0 = (b / ktiles) * 32;
    const int tx = threadIdx.x, ty = threadIdx.y;
#pragma unroll
    for (int i = 0; i < 4; i++)
        t[ty + 8 * i][tx] = W[(size_t)(k0 + ty + 8 * i) * 128 + n0 + tx];
    __syncthreads();
#pragma unroll
    for (int i = 0; i < 4; i++)
        out[(size_t)(n0 + ty + 8 * i) * K + k0 + tx] = t[tx][ty + 8 * i];
}

// =================================================================
// GEMM body: C[M,128] = act( A1[M,K1]@B1 + A2[M,K2]@B2 + bias )
// BT = pre-transposed weights [128][Kb], Kb = K1+K2.
// 512 threads, 4x4 warp grid, 32x32 warp tile, 2-stage cp.async.
// =================================================================
__device__ __forceinline__ void gemm_body(
    const float* __restrict__ A1, int K1,
    const float* __restrict__ A2, int K2,
    const float* __restrict__ BT, int Kb,
    const float* __restrict__ bias, float* __restrict__ C, int M, int doRelu,
    int m0, char* smem_raw)
{
    float (*As)[128][AS_F] = (float(*)[128][AS_F])smem_raw;
    float (*Bs)[128][BS_F] = (float(*)[128][BS_F])(smem_raw + AS_BYTES);
    float* bias_s          = (float*)(smem_raw + AS_BYTES + BS_BYTES);

    const int tid = threadIdx.x;
    if (tid < 128) bias_s[tid] = bias[tid];

    const int warp = tid >> 5, lane = tid & 31;
    const int wm = warp & 3, wn = warp >> 2;
    const int grp = lane >> 2, tg = lane & 3;

    const int nch1 = K1 >> 5;
    const int nch  = Kb >> 5;

    auto stage = [&](int c, int buf) {
        const float* A; int K, ka;
        if (c < nch1) { A = A1; K = K1; ka = c * 32; }
        else          { A = A2; K = K2; ka = c * 32 - K1; }
        const int kkb = c * 32;
#pragma unroll
        for (int i = 0; i < 2; i++) {
            int slot = tid + i * 512;
            int r = slot >> 3, c4 = (slot & 7) * 4;
            int grow = m0 + r;
            int ok = (grow < M);
            cp16(sa(&As[buf][r][c4]), A + (size_t)(ok ? grow : 0) * K + ka + c4, ok ? 16 : 0);
        }
#pragma unroll
        for (int i = 0; i < 2; i++) {
            int slot = tid + i * 512;
            int r = slot >> 3, c4 = (slot & 7) * 4;
            cp16(sa(&Bs[buf][r][c4]), BT + (size_t)r * Kb + kkb + c4, 16);
        }
        cp_commit();
    };

    float acc[2][4][4];
#pragma unroll
    for (int a = 0; a < 2; a++)
#pragma unroll
        for (int b = 0; b < 4; b++)
#pragma unroll
            for (int k = 0; k < 4; k++) acc[a][b][k] = 0.f;

    stage(0, 0);

    for (int c = 0; c < nch; c++) {
        const int buf = c & 1;
        if (c + 1 < nch) { stage(c + 1, buf ^ 1); cp_wait1(); }
        else             { cp_wait0(); }
        __syncthreads();

#pragma unroll
        for (int ks = 0; ks < 2; ks++) {
            const int kb = ks * 16;
            uint32_t af[2][4];
#pragma unroll
            for (int mt = 0; mt < 2; mt++) {
                int r0 = wm * 32 + mt * 16 + grp;
                af[mt][0] = f2h2v(*(const float2*)&As[buf][r0][kb + 2 * tg]);
                af[mt][1] = f2h2v(*(const float2*)&As[buf][r0 + 8][kb + 2 * tg]);
                af[mt][2] = f2h2v(*(const float2*)&As[buf][r0][kb + 2 * tg + 8]);
                af[mt][3] = f2h2v(*(const float2*)&As[buf][r0 + 8][kb + 2 * tg + 8]);
            }
#pragma unroll
            for (int nt = 0; nt < 4; nt++) {
                int cc = wn * 32 + nt * 8 + grp;
                uint32_t bf[2];
                bf[0] = f2h2v(*(const float2*)&Bs[buf][cc][kb + 2 * tg]);
                bf[1] = f2h2v(*(const float2*)&Bs[buf][cc][kb + 2 * tg + 8]);
                mma16(acc[0][nt], af[0], bf);
                mma16(acc[1][nt], af[1], bf);
            }
        }
        __syncthreads();
    }

#pragma unroll
    for (int mt = 0; mt < 2; mt++) {
#pragma unroll
        for (int half = 0; half < 2; half++) {
            int grow = m0 + wm * 32 + mt * 16 + half * 8 + grp;
            if (grow < M) {
#pragma unroll
                for (int nt = 0; nt < 4; nt++) {
                    int cc = wn * 32 + nt * 8 + tg * 2;
                    float v0 = acc[mt][nt][half * 2 + 0] + bias_s[cc];
                    float v1 = acc[mt][nt][half * 2 + 1] + bias_s[cc + 1];
                    if (doRelu) { v0 = fmaxf(v0, 0.f); v1 = fmaxf(v1, 0.f); }
                    float2 o; o.x = v0; o.y = v1;
                    *(float2*)(C + (size_t)grow * 128 + cc) = o;
                }
            }
        }
    }
}

__global__ __launch_bounds__(512, 2) void gemm128(
    const float* __restrict__ A1, int K1,
    const float* __restrict__ A2, int K2,
    const float* __restrict__ BT, int Kb,
    const float* __restrict__ bias, float* __restrict__ C, int M, int doRelu)
{
    extern __shared__ char smem_raw[];
    gemm_body(A1, K1, A2, K2, BT, Kb, bias, C, M, doRelu, blockIdx.x * 128, smem_raw);
}

// node projections merged: blocks [0,half) -> left, [half,2*half) -> right
__global__ __launch_bounds__(512, 2) void gemm_dual(
    const float* __restrict__ Aa, const float* __restrict__ BTa,
    const float* __restrict__ ba, float* __restrict__ Ca,
    const float* __restrict__ Ab, const float* __restrict__ BTb,
    const float* __restrict__ bb, float* __restrict__ Cb,
    int M, int half)
{
    extern __shared__ char smem_raw[];
    if (blockIdx.x < half)
        gemm_body(Aa, 128, nullptr, 0, BTa, 128, ba, Ca, M, 0,
                  blockIdx.x * 128, smem_raw);
    else
        gemm_body(Ab, 128, nullptr, 0, BTb, 128, bb, Cb, M, 0,
                  (blockIdx.x - half) * 128, smem_raw);
}

// =================================================================
// Fused edge kernel: eproj = EF @ W_e (fp16 mma, never materialized),
// z = leakyrelu(eproj + x_l[src] + x_r[dst], 0.2),
// logits[e,h] = z_h . att_h  -> g_logits[E][4]
// 512 threads, 4x4 warp grid; each warp covers exactly one head.
// =================================================================
__global__ __launch_bounds__(512, 2) void edge_logits_kernel(
    const float* __restrict__ EF, const float* __restrict__ WeT,
    const int* __restrict__ src, const int* __restrict__ dst,
    const float* __restrict__ att)
{
    extern __shared__ char smem_raw[];
    float (*As)[128][AS_F] = (float(*)[128][AS_F])smem_raw;
    float (*Bs)[128][BS_F] = (float(*)[128][BS_F])(smem_raw + AS_BYTES);
    int*   src_s = (int*)(smem_raw + AS_BYTES + BS_BYTES);
    int*   dst_s = src_s + 128;
    float* att_s = (float*)(dst_s + 128);

    const int tid = threadIdx.x;
    const int e0  = blockIdx.x * 128;

    if (tid < 128) {
        src_s[tid] = src[e0 + tid];
        dst_s[tid] = dst[e0 + tid];
        att_s[tid] = att[tid];
    }

    const int warp = tid >> 5, lane = tid & 31;
    const int wm = warp & 3, wn = warp >> 2;
    const int grp = lane >> 2, tg = lane & 3;

    auto stage = [&](int c, int buf) {
        const int kk = c * 32;
#pragma unroll
        for (int i = 0; i < 2; i++) {
            int slot = tid + i * 512;
            int r = slot >> 3, c4 = (slot & 7) * 4;
            cp16(sa(&As[buf][r][c4]), EF + (size_t)(e0 + r) * 128 + kk + c4, 16);
        }
#pragma unroll
        for (int i = 0; i < 2; i++) {
            int slot = tid + i * 512;
            int r = slot >> 3, c4 = (slot & 7) * 4;
            cp16(sa(&Bs[buf][r][c4]), WeT + (size_t)r * 128 + kk + c4, 16);
        }
        cp_commit();
    };

    float acc[2][4][4];
#pragma unroll
    for (int a = 0; a < 2; a++)
#pragma unroll
        for (int b = 0; b < 4; b++)
#pragma unroll
            for (int k = 0; k < 4; k++) acc[a][b][k] = 0.f;

    stage(0, 0);

#pragma unroll
    for (int c = 0; c < 4; c++) {
        const int buf = c & 1;
        if (c < 3) { stage(c + 1, buf ^ 1); cp_wait1(); }
        else       { cp_wait0(); }
        __syncthreads();

#pragma unroll
        for (int ks = 0; ks < 2; ks++) {
            const int kb = ks * 16;
            uint32_t af[2][4];
#pragma unroll
            for (int mt = 0; mt < 2; mt++) {
                int r0 = wm * 32 + mt * 16 + grp;
                af[mt][0] = f2h2v(*(const float2*)&As[buf][r0][kb + 2 * tg]);
                af[mt][1] = f2h2v(*(const float2*)&As[buf][r0 + 8][kb + 2 * tg]);
                af[mt][2] = f2h2v(*(const float2*)&As[buf][r0][kb + 2 * tg + 8]);
                af[mt][3] = f2h2v(*(const float2*)&As[buf][r0 + 8][kb + 2 * tg + 8]);
            }
#pragma unroll
            for (int nt = 0; nt < 4; nt++) {
                int cc = wn * 32 + nt * 8 + grp;
                uint32_t bf[2];
                bf[0] = f2h2v(*(const float2*)&Bs[buf][cc][kb + 2 * tg]);
                bf[1] = f2h2v(*(const float2*)&Bs[buf][cc][kb + 2 * tg + 8]);
                mma16(acc[0][nt], af[0], bf);
                mma16(acc[1][nt], af[1], bf);
            }
        }
        __syncthreads();
    }

    // epilogue: gather x_l[src], x_r[dst], leaky-relu, att-dot; head = wn
#pragma unroll
    for (int mt = 0; mt < 2; mt++) {
#pragma unroll
        for (int half = 0; half < 2; half++) {
            int row = wm * 32 + mt * 16 + half * 8 + grp;
            const float* xl = g_xl + (size_t)src_s[row] * 128;
            const float* xr = g_xr + (size_t)dst_s[row] * 128;
            float partial = 0.f;
#pragma unroll
            for (int nt = 0; nt < 4; nt++) {
                int col = wn * 32 + nt * 8 + tg * 2;
                float2 a = *(const float2*)(xl + col);
                float2 b = *(const float2*)(xr + col);
                float z0 = acc[mt][nt][half * 2 + 0] + a.x + b.x;
                float z1 = acc[mt][nt][half * 2 + 1] + a.y + b.y;
                z0 = (z0 > 0.f) ? z0 : 0.2f * z0;
                z1 = (z1 > 0.f) ? z1 : 0.2f * z1;
                partial += z0 * att_s[col] + z1 * att_s[col + 1];
            }
            partial += __shfl_xor_sync(0xFFFFFFFFu, partial, 1);
            partial += __shfl_xor_sync(0xFFFFFFFFu, partial, 2);
            if (tg == 0)
                g_logits[(size_t)(e0 + row) * 4 + wn] = partial;
        }
    }
}

// ---------------- CSR build ----------------
__global__ void zero_cnt_kernel() {
    int i = blockIdx.x * blockDim.x + threadIdx.x;
    if (i < NLR) g_cnt[i] = 0;
}

__global__ void count_kernel(const int* __restrict__ dst) {
    int e = blockIdx.x * blockDim.x + threadIdx.x;
    if (e < ENUM) atomicAdd(&g_cnt[dst[e]], 1);
}

__global__ __launch_bounds__(1024) void scan_kernel() {
    __shared__ int part[1024];
    const int t = threadIdx.x;
    const int CH = (NLR + 1023) / 1024;
    int start = t * CH, end = min(start + CH, NLR);
    int s = 0;
    for (int i = start; i < end; i++) s += g_cnt[i];
    part[t] = s;
    __syncthreads();
    for (int off = 1; off < 1024; off <<= 1) {
        int v = (t >= off) ? part[t - off] : 0;
        __syncthreads();
        part[t] += v;
        __syncthreads();
    }
    int run = part[t] - s;
    for (int i = start; i < end; i++) {
        g_off[i] = run; g_cur[i] = run;
        run += g_cnt[i];
    }
    if (t == 1023) g_off[NLR] = part[1023];
}

__global__ void fill_kernel(const int* __restrict__ dst) {
    int e = blockIdx.x * blockDim.x + threadIdx.x;
    if (e < ENUM) {
        int p = atomicAdd(&g_cur[dst[e]], 1);
        g_elist[p] = e;
    }
}

// =================================================================
// Warp-per-node fused segment softmax + message + b_conv + LayerNorm.
// Lane l owns channels [4l, 4l+4), head = l>>3. No smem, no barriers.
// =================================================================
__global__ __launch_bounds__(256) void message_ln_kernel(
    const int* __restrict__ src,
    const float* __restrict__ bconv,
    const float* __restrict__ lng, const float* __restrict__ lnb)
{
    const int node = (blockIdx.x * blockDim.x + threadIdx.x) >> 5;
    const int lane = threadIdx.x & 31;
    if (node >= NLR) return;

    const int h  = lane >> 3;
    const int c4 = lane * 4;
    const int off0 = g_off[node];
    const int deg  = g_off[node + 1] - off0;

    float4 mx = make_float4(-1e30f, -1e30f, -1e30f, -1e30f);
    for (int i = lane; i < deg; i += 32) {
        int e = __ldg(&g_elist[off0 + i]);
        float4 lg = *(const float4*)&g_logits[(size_t)e * 4];
        mx.x = fmaxf(mx.x, lg.x); mx.y = fmaxf(mx.y, lg.y);
        mx.z = fmaxf(mx.z, lg.z); mx.w = fmaxf(mx.w, lg.w);
    }
#pragma unroll
    for (int o = 16; o; o >>= 1) {
        mx.x = fmaxf(mx.x, __shfl_xor_sync(0xFFFFFFFFu, mx.x, o));
        mx.y = fmaxf(mx.y, __shfl_xor_sync(0xFFFFFFFFu, mx.y, o));
        mx.z = fmaxf(mx.z, __shfl_xor_sync(0xFFFFFFFFu, mx.z, o));
        mx.w = fmaxf(mx.w, __shfl_xor_sync(0xFFFFFFFFu, mx.w, o));
    }

    float4 sm = make_float4(0.f, 0.f, 0.f, 0.f);
    for (int i = lane; i < deg; i += 32) {
        int e = __ldg(&g_elist[off0 + i]);
        float4 lg = *(const float4*)&g_logits[(size_t)e * 4];
        sm.x += __expf(lg.x - mx.x); sm.y += __expf(lg.y - mx.y);
        sm.z += __expf(lg.z - mx.z); sm.w += __expf(lg.w - mx.w);
    }
#pragma unroll
    for (int o = 16; o; o >>= 1) {
        sm.x += __shfl_xor_sync(0xFFFFFFFFu, sm.x, o);
        sm.y += __shfl_xor_sync(0xFFFFFFFFu, sm.y, o);
        sm.z += __shfl_xor_sync(0xFFFFFFFFu, sm.z, o);
        sm.w += __shfl_xor_sync(0xFFFFFFFFu, sm.w, o);
    }

    const float m_h = (h == 0) ? mx.x : (h == 1) ? mx.y : (h == 2) ? mx.z : mx.w;
    const float s_h = (h == 0) ? sm.x : (h == 1) ? sm.y : (h == 2) ? sm.z : sm.w;
    const float inv_h = 1.f / (s_h + 1e-16f);

    float4 acc = make_float4(0.f, 0.f, 0.f, 0.f);
    for (int j = 0; j < deg; j++) {
        int e  = __ldg(&g_elist[off0 + j]);
        int sr = __ldg(&src[e]);
        float a = __expf(__ldg(&g_logits[(size_t)e * 4 + h]) - m_h);
        float4 x = *(const float4*)&g_xl[(size_t)sr * 128 + c4];
        acc.x = fmaf(a, x.x, acc.x); acc.y = fmaf(a, x.y, acc.y);
        acc.z = fmaf(a, x.z, acc.z); acc.w = fmaf(a, x.w, acc.w);
    }
    float4 bc = *(const float4*)&bconv[c4];
    float4 msg;
    msg.x = acc.x * inv_h + bc.x; msg.y = acc.y * inv_h + bc.y;
    msg.z = acc.z * inv_h + bc.z; msg.w = acc.w * inv_h + bc.w;

    float s1 = msg.x + msg.y + msg.z + msg.w;
    float s2 = msg.x * msg.x + msg.y * msg.y + msg.z * msg.z + msg.w * msg.w;
#pragma unroll
    for (int o = 16; o; o >>= 1) {
        s1 += __shfl_xor_sync(0xFFFFFFFFu, s1, o);
        s2 += __shfl_xor_sync(0xFFFFFFFFu, s2, o);
    }
    float mu  = s1 * (1.f / 128.f);
    float var = fmaxf(s2 * (1.f / 128.f) - mu * mu, 0.f);
    float r = rsqrtf(var + 1e-5f);

    float4 g = *(const float4*)&lng[c4];
    float4 b = *(const float4*)&lnb[c4];
    float4 o4;
    o4.x = (msg.x - mu) * r * g.x + b.x;
    o4.y = (msg.y - mu) * r * g.y + b.y;
    o4.z = (msg.z - mu) * r * g.z + b.z;
    o4.w = (msg.w - mu) * r * g.w + b.w;
    *(float4*)&g_ln[(size_t)node * 128 + c4] = o4;
}

// =================================================================
extern "C" void kernel_launch(void* const* d_in, const int* in_sizes, int n_in,
                              void* d_out, int out_size) {
    const float* left  = (const float*)d_in[0];
    const int*   eidx  = (const int*)d_in[1];
    const float* ef    = (const float*)d_in[2];
    const float* right = (const float*)d_in[3];
    const float* W_l   = (const float*)d_in[4];
    const float* b_l   = (const float*)d_in[5];
    const float* W_r   = (const float*)d_in[6];
    const float* b_r   = (const float*)d_in[7];
    const float* W_e   = (const float*)d_in[8];
    const float* att   = (const float*)d_in[9];
    const float* bconv = (const float*)d_in[10];
    const float* ln_g  = (const float*)d_in[11];
    const float* ln_b  = (const float*)d_in[12];
    const float* W1    = (const float*)d_in[13];
    const float* b1    = (const float*)d_in[14];
    const float* W2    = (const float*)d_in[15];
    const float* b2    = (const float*)d_in[16];
    float* out = (float*)d_out;

    const int* src = eidx;
    const int* dst = eidx + ENUM;

    float* xl; cudaGetSymbolAddress((void**)&xl, g_xl);
    float* xr; cudaGetSymbolAddress((void**)&xr, g_xr);
    float* ln; cudaGetSymbolAddress((void**)&ln, g_ln);
    float* h1; cudaGetSymbolAddress((void**)&h1, g_h1);
    float* wT; cudaGetSymbolAddress((void**)&wT, g_wT);

    cudaFuncSetAttribute(gemm128,
                         cudaFuncAttributeMaxDynamicSharedMemorySize, SMEM_GEMM);
    cudaFuncSetAttribute(gemm_dual,
                         cudaFuncAttributeMaxDynamicSharedMemorySize, SMEM_GEMM);
    cudaFuncSetAttribute(edge_logits_kernel,
                         cudaFuncAttributeMaxDynamicSharedMemorySize, SMEM_EDGE);

    const int gblk = (NLR + 127) / 128;   // 391

    // 1: one-time weight transposes
    transpose5<<<96, dim3(32, 8)>>>(W_l, W_r, W_e, W1, W2);
    // 2: counter init (independent)
    zero_cnt_kernel<<<(NLR + 255) / 256, 256>>>();
    // 3: node projections
    gemm_dual<<<2 * gblk, 512, SMEM_GEMM>>>(left, wT + WL_T, b_l, xl,
                                            right, wT + WR_T, b_r, xr, NLR, gblk);
    // 4: edge logits — profiled slot
    edge_logits_kernel<<<ENUM / 128, 512, SMEM_EDGE>>>(ef, wT + WE_T, src, dst, att);
    // 5-7: CSR build
    count_kernel<<<(ENUM + 255) / 256, 256>>>(dst);
    scan_kernel<<<1, 1024>>>();
    fill_kernel<<<(ENUM + 255) / 256, 256>>>(dst);
    // 8: warp-per-node segment softmax + message + LN
    message_ln_kernel<<<(NLR * 32 + 255) / 256, 256>>>(src, bconv, ln_g, ln_b);
    // 9-10: out MLP
    gemm128<<<gblk, 512, SMEM_GEMM>>>(ln, 128, right, 128, wT + W1_T, 256,
                                      b1, h1, NLR, 1);
    gemm128<<<gblk, 512, SMEM_GEMM>>>(h1, 128, nullptr, 0, wT + W2_T, 128,
                                      b2, out, NLR, 0);
}

// round 9
// speedup vs baseline: 1.2383x; 1.2383x over previous
#include <cuda_runtime.h>
#include <cuda_fp16.h>
#include <math.h>
#include <stdint.h>

#define NLR  50000
#define EMBD 128
#define ENUM 800000

#define AH_S 40   // Ash row stride (halves): 20 words -> conflict-free frags
#define BH_S 40   // Bsh row stride (halves)

// ---------------- device scratch (no allocations allowed) ----------------
__device__ float  g_logits[(size_t)ENUM * 4];
__device__ __half g_xlh[(size_t)NLR * EMBD];
__device__ __half g_xrh[(size_t)NLR * EMBD];
__device__ float  g_ln[(size_t)NLR * EMBD];
__device__ float  g_h1[(size_t)NLR * EMBD];
__device__ __half g_wTh[128 * 768];          // wlT|wrT|weT|w1T(128x256)|w2T
__device__ int    g_cnt[NLR];
__device__ int    g_off[NLR + 1];
__device__ int    g_cur[NLR];
__device__ int    g_elist[ENUM];

#define WL_T 0
#define WR_T 16384
#define WE_T 32768
#define W1_T 49152
#define W2_T 81920

// ---------------- helpers ----------------
__device__ __forceinline__ void mma16(float c[4], const uint32_t a[4], const uint32_t b[2]) {
    asm volatile(
        "mma.sync.aligned.m16n8k16.row.col.f32.f16.f16.f32 "
        "{%0,%1,%2,%3},{%4,%5,%6,%7},{%8,%9},{%0,%1,%2,%3};\n"
        : "+f"(c[0]), "+f"(c[1]), "+f"(c[2]), "+f"(c[3])
        : "r"(a[0]), "r"(a[1]), "r"(a[2]), "r"(a[3]), "r"(b[0]), "r"(b[1]));
}

__device__ __forceinline__ void cp16(uint32_t saddr, const void* gptr, int sz) {
    asm volatile("cp.async.cg.shared.global [%0], [%1], 16, %2;\n"
                 :: "r"(saddr), "l"(gptr), "r"(sz));
}
__device__ __forceinline__ void cp_commit() { asm volatile("cp.async.commit_group;\n"); }
__device__ __forceinline__ void cp_wait1()  { asm volatile("cp.async.wait_group 1;\n"); }
__device__ __forceinline__ void cp_wait0()  { asm volatile("cp.async.wait_group 0;\n"); }
__device__ __forceinline__ uint32_t sa(const void* p) {
    return (uint32_t)__cvta_generic_to_shared(p);
}
__device__ __forceinline__ uint32_t ldh2(const __half* p) { return *(const uint32_t*)p; }

#define ASH_BYTES (2 * 128 * AH_S * 2)   // 20480
#define BSH_BYTES (2 * 128 * BH_S * 2)   // 20480
#define SMEM_GEMM (ASH_BYTES + BSH_BYTES + 512)
#define SMEM_EDGE (ASH_BYTES + BSH_BYTES + 128 * 4 * 2 + 512)

// =================================================================
// one-time weight transpose + fp16 convert: g_wTh[n][k] = h(W[k][n])
// =================================================================
__global__ void transpose5(const float* __restrict__ Wl, const float* __restrict__ Wr,
                           const float* __restrict__ We, const float* __restrict__ W1,
                           const float* __restrict__ W2) {
    __shared__ float t[32][33];
    int b = blockIdx.x;
    const float* W; __half* out; int K;
    if      (b < 16) { W = Wl; out = g_wTh + WL_T; K = 128; }
    else if (b < 32) { W = Wr; out = g_wTh + WR_T; K = 128; b -= 16; }
    else if (b < 48) { W = We; out = g_wTh + WE_T; K = 128; b -= 32; }
    else if (b < 80) { W = W1; out = g_wTh + W1_T; K = 256; b -= 48; }
    else             { W = W2; out = g_wTh + W2_T; K = 128; b -= 80; }
    const int ktiles = K >> 5;
    const int k0 = (b % ktiles) * 32, n0 = (b / ktiles) * 32;
    const int tx = threadIdx.x, ty = threadIdx.y;
#pragma unroll
    for (int i = 0; i < 4; i++)
        t[ty + 8 * i][tx] = W[(size_t)(k0 + ty + 8 * i) * 128 + n0 + tx];
    __syncthreads();
#pragma unroll
    for (int i = 0; i < 4; i++)
        out[(size_t)(n0 + ty + 8 * i) * K + k0 + tx] = __float2half(t[tx][ty + 8 * i]);
}

// =================================================================
// GEMM body: C[M,128] = act( [A1|A2](M, K1+K2) @ BT^T + bias )
// BT: fp16 pre-transposed [128][Kb]. A: fp32 global, LDG->cvt->STS fp16.
// 512 threads, 4x4 warp grid, 32x32 warp tiles, fp16 smem operands.
// HALF_OUT: write half2 to Ch instead of float to C.
// =================================================================
template <bool HALF_OUT>
__device__ __forceinline__ void gemm_body(
    const float* __restrict__ A1, int K1,
    const float* __restrict__ A2, int K2,
    const __half* __restrict__ BT, int Kb,
    const float* __restrict__ bias, float* __restrict__ C, __half* __restrict__ Ch,
    int M, int doRelu, int m0, char* smem_raw)
{
    __half (*Ash)[128][AH_S] = (__half(*)[128][AH_S])smem_raw;
    __half (*Bsh)[128][BH_S] = (__half(*)[128][BH_S])(smem_raw + ASH_BYTES);
    float* bias_s            = (float*)(smem_raw + ASH_BYTES + BSH_BYTES);

    const int tid = threadIdx.x;
    if (tid < 128) bias_s[tid] = bias[tid];

    const int warp = tid >> 5, lane = tid & 31;
    const int wm = warp & 3, wn = warp >> 2;
    const int grp = lane >> 2, tg = lane & 3;

    const int nch1 = K1 >> 5;
    const int nch  = Kb >> 5;

    // A LDG coords: slot = tid + i*512 -> row = slot>>3, col4 = (slot&7)*4
    const int ar0 = tid >> 3, ac = (tid & 7) * 4;

    auto ldgA = [&](int c, float4& a0, float4& a1) {
        const float* A; int K, ka;
        if (c < nch1) { A = A1; K = K1; ka = c * 32; }
        else          { A = A2; K = K2; ka = c * 32 - K1; }
        int g0 = m0 + ar0, g1 = m0 + ar0 + 64;
        a0 = (g0 < M) ? *(const float4*)(A + (size_t)g0 * K + ka + ac)
                      : make_float4(0.f, 0.f, 0.f, 0.f);
        a1 = (g1 < M) ? *(const float4*)(A + (size_t)g1 * K + ka + ac)
                      : make_float4(0.f, 0.f, 0.f, 0.f);
    };
    auto stsA = [&](int buf, const float4& a0, const float4& a1) {
        __half2 h0 = __floats2half2_rn(a0.x, a0.y), h1 = __floats2half2_rn(a0.z, a0.w);
        *(uint2*)&Ash[buf][ar0][ac]      = make_uint2(*(uint32_t*)&h0, *(uint32_t*)&h1);
        __half2 h2 = __floats2half2_rn(a1.x, a1.y), h3 = __floats2half2_rn(a1.z, a1.w);
        *(uint2*)&Ash[buf][ar0 + 64][ac] = make_uint2(*(uint32_t*)&h2, *(uint32_t*)&h3);
    };
    // B cp.async: slot = tid -> row = tid>>2, 16B unit = (tid&3)*8 halves
    const int br = tid >> 2, bu = (tid & 3) * 8;
    auto stageB = [&](int c, int buf) {
        cp16(sa(&Bsh[buf][br][bu]), BT + (size_t)br * Kb + c * 32 + bu, 16);
        cp_commit();
    };

    float acc[2][4][4];
#pragma unroll
    for (int a = 0; a < 2; a++)
#pragma unroll
        for (int b = 0; b < 4; b++)
#pragma unroll
            for (int k = 0; k < 4; k++) acc[a][b][k] = 0.f;

    float4 a0, a1;
    ldgA(0, a0, a1);
    stageB(0, 0);

    for (int c = 0; c < nch; c++) {
        const int buf = c & 1;
        __syncthreads();                       // prev compute done (buffers reusable)
        stsA(buf, a0, a1);
        if (c + 1 < nch) {
            stageB(c + 1, buf ^ 1);
            ldgA(c + 1, a0, a1);
            cp_wait1();                        // B(c) arrived
        } else {
            cp_wait0();
        }
        __syncthreads();                       // Ash/Bsh[buf] visible to all

#pragma unroll
        for (int ks = 0; ks < 2; ks++) {
            const int kb = ks * 16;
            uint32_t af[2][4];
#pragma unroll
            for (int mt = 0; mt < 2; mt++) {
                int r0 = wm * 32 + mt * 16 + grp;
                af[mt][0] = ldh2(&Ash[buf][r0][kb + 2 * tg]);
                af[mt][1] = ldh2(&Ash[buf][r0 + 8][kb + 2 * tg]);
                af[mt][2] = ldh2(&Ash[buf][r0][kb + 2 * tg + 8]);
                af[mt][3] = ldh2(&Ash[buf][r0 + 8][kb + 2 * tg + 8]);
            }
#pragma unroll
            for (int nt = 0; nt < 4; nt++) {
                int cc = wn * 32 + nt * 8 + grp;
                uint32_t bf[2];
                bf[0] = ldh2(&Bsh[buf][cc][kb + 2 * tg]);
                bf[1] = ldh2(&Bsh[buf][cc][kb + 2 * tg + 8]);
                mma16(acc[0][nt], af[0], bf);
                mma16(acc[1][nt], af[1], bf);
            }
        }
    }

#pragma unroll
    for (int mt = 0; mt < 2; mt++) {
#pragma unroll
        for (int half = 0; half < 2; half++) {
            int grow = m0 + wm * 32 + mt * 16 + half * 8 + grp;
            if (grow < M) {
#pragma unroll
                for (int nt = 0; nt < 4; nt++) {
                    int cc = wn * 32 + nt * 8 + tg * 2;
                    float v0 = acc[mt][nt][half * 2 + 0] + bias_s[cc];
                    float v1 = acc[mt][nt][half * 2 + 1] + bias_s[cc + 1];
                    if (doRelu) { v0 = fmaxf(v0, 0.f); v1 = fmaxf(v1, 0.f); }
                    if (HALF_OUT) {
                        __half2 h = __floats2half2_rn(v0, v1);
                        *(__half2*)(Ch + (size_t)grow * 128 + cc) = h;
                    } else {
                        float2 o; o.x = v0; o.y = v1;
                        *(float2*)(C + (size_t)grow * 128 + cc) = o;
                    }
                }
            }
        }
    }
}

__global__ __launch_bounds__(512, 2) void gemm128(
    const float* __restrict__ A1, int K1,
    const float* __restrict__ A2, int K2,
    const __half* __restrict__ BT, int Kb,
    const float* __restrict__ bias, float* __restrict__ C, int M, int doRelu)
{
    extern __shared__ char smem_raw[];
    gemm_body<false>(A1, K1, A2, K2, BT, Kb, bias, C, nullptr, M, doRelu,
                     blockIdx.x * 128, smem_raw);
}

// node projections merged, half output to g_xlh / g_xrh
__global__ __launch_bounds__(512, 2) void gemm_dual(
    const float* __restrict__ Aa, const __half* __restrict__ BTa,
    const float* __restrict__ ba,
    const float* __restrict__ Ab, const __half* __restrict__ BTb,
    const float* __restrict__ bb,
    int M, int half)
{
    extern __shared__ char smem_raw[];
    if (blockIdx.x < half)
        gemm_body<true>(Aa, 128, nullptr, 0, BTa, 128, ba, nullptr, g_xlh, M, 0,
                        blockIdx.x * 128, smem_raw);
    else
        gemm_body<true>(Ab, 128, nullptr, 0, BTb, 128, bb, nullptr, g_xrh, M, 0,
                        (blockIdx.x - half) * 128, smem_raw);
}

// =================================================================
// Fused edge kernel: eproj = EF @ W_e (fp16 smem operands),
// z = leakyrelu(eproj + x_l[src] + x_r[dst], 0.2),
// logits[e,h] = z_h . att_h  -> g_logits[E][4]; head = wn.
// =================================================================
__global__ __launch_bounds__(512, 2) void edge_logits_kernel(
    const float* __restrict__ EF, const __half* __restrict__ WeT,
    const int* __restrict__ src, const int* __restrict__ dst,
    const float* __restrict__ att)
{
    extern __shared__ char smem_raw[];
    __half (*Ash)[128][AH_S] = (__half(*)[128][AH_S])smem_raw;
    __half (*Bsh)[128][BH_S] = (__half(*)[128][BH_S])(smem_raw + ASH_BYTES);
    int*   src_s = (int*)(smem_raw + ASH_BYTES + BSH_BYTES);
    int*   dst_s = src_s + 128;
    float* att_s = (float*)(dst_s + 128);

    const int tid = threadIdx.x;
    const int e0  = blockIdx.x * 128;

    if (tid < 128) {
        src_s[tid] = src[e0 + tid];
        dst_s[tid] = dst[e0 + tid];
        att_s[tid] = att[tid];
    }

    const int warp = tid >> 5, lane = tid & 31;
    const int wm = warp & 3, wn = warp >> 2;
    const int grp = lane >> 2, tg = lane & 3;

    const int ar0 = tid >> 3, ac = (tid & 7) * 4;
    const int br = tid >> 2, bu = (tid & 3) * 8;

    auto ldgA = [&](int c, float4& a0, float4& a1) {
        const int ka = c * 32;
        a0 = *(const float4*)(EF + (size_t)(e0 + ar0) * 128 + ka + ac);
        a1 = *(const float4*)(EF + (size_t)(e0 + ar0 + 64) * 128 + ka + ac);
    };
    auto stsA = [&](int buf, const float4& a0, const float4& a1) {
        __half2 h0 = __floats2half2_rn(a0.x, a0.y), h1 = __floats2half2_rn(a0.z, a0.w);
        *(uint2*)&Ash[buf][ar0][ac]      = make_uint2(*(uint32_t*)&h0, *(uint32_t*)&h1);
        __half2 h2 = __floats2half2_rn(a1.x, a1.y), h3 = __floats2half2_rn(a1.z, a1.w);
        *(uint2*)&Ash[buf][ar0 + 64][ac] = make_uint2(*(uint32_t*)&h2, *(uint32_t*)&h3);
    };
    auto stageB = [&](int c, int buf) {
        cp16(sa(&Bsh[buf][br][bu]), WeT + (size_t)br * 128 + c * 32 + bu, 16);
        cp_commit();
    };

    float acc[2][4][4];
#pragma unroll
    for (int a = 0; a < 2; a++)
#pragma unroll
        for (int b = 0; b < 4; b++)
#pragma unroll
            for (int k = 0; k < 4; k++) acc[a][b][k] = 0.f;

    float4 a0, a1;
    ldgA(0, a0, a1);
    stageB(0, 0);

#pragma unroll
    for (int c = 0; c < 4; c++) {
        const int buf = c & 1;
        __syncthreads();
        stsA(buf, a0, a1);
        if (c + 1 < 4) {
            stageB(c + 1, buf ^ 1);
            ldgA(c + 1, a0, a1);
            cp_wait1();
        } else {
            cp_wait0();
        }
        __syncthreads();

#pragma unroll
        for (int ks = 0; ks < 2; ks++) {
            const int kb = ks * 16;
            uint32_t af[2][4];
#pragma unroll
            for (int mt = 0; mt < 2; mt++) {
                int r0 = wm * 32 + mt * 16 + grp;
                af[mt][0] = ldh2(&Ash[buf][r0][kb + 2 * tg]);
                af[mt][1] = ldh2(&Ash[buf][r0 + 8][kb + 2 * tg]);
                af[mt][2] = ldh2(&Ash[buf][r0][kb + 2 * tg + 8]);
                af[mt][3] = ldh2(&Ash[buf][r0 + 8][kb + 2 * tg + 8]);
            }
#pragma unroll
            for (int nt = 0; nt < 4; nt++) {
                int cc = wn * 32 + nt * 8 + grp;
                uint32_t bf[2];
                bf[0] = ldh2(&Bsh[buf][cc][kb + 2 * tg]);
                bf[1] = ldh2(&Bsh[buf][cc][kb + 2 * tg + 8]);
                mma16(acc[0][nt], af[0], bf);
                mma16(acc[1][nt], af[1], bf);
            }
        }
    }

    // epilogue: fp16 gathers of x_l[src], x_r[dst]; head = wn
#pragma unroll
    for (int mt = 0; mt < 2; mt++) {
#pragma unroll
        for (int half = 0; half < 2; half++) {
            int row = wm * 32 + mt * 16 + half * 8 + grp;
            const __half* xl = g_xlh + (size_t)src_s[row] * 128;
            const __half* xr = g_xrh + (size_t)dst_s[row] * 128;
            float partial = 0.f;
#pragma unroll
            for (int nt = 0; nt < 4; nt++) {
                int col = wn * 32 + nt * 8 + tg * 2;
                float2 a = __half22float2(*(const __half2*)(xl + col));
                float2 b = __half22float2(*(const __half2*)(xr + col));
                float z0 = acc[mt][nt][half * 2 + 0] + a.x + b.x;
                float z1 = acc[mt][nt][half * 2 + 1] + a.y + b.y;
                z0 = (z0 > 0.f) ? z0 : 0.2f * z0;
                z1 = (z1 > 0.f) ? z1 : 0.2f * z1;
                partial += z0 * att_s[col] + z1 * att_s[col + 1];
            }
            partial += __shfl_xor_sync(0xFFFFFFFFu, partial, 1);
            partial += __shfl_xor_sync(0xFFFFFFFFu, partial, 2);
            if (tg == 0)
                g_logits[(size_t)(e0 + row) * 4 + wn] = partial;
        }
    }
}

// ---------------- CSR build ----------------
__global__ void zero_cnt_kernel() {
    int i = blockIdx.x * blockDim.x + threadIdx.x;
    if (i < NLR) g_cnt[i] = 0;
}

__global__ void count_kernel(const int* __restrict__ dst) {
    int e = blockIdx.x * blockDim.x + threadIdx.x;
    if (e < ENUM) atomicAdd(&g_cnt[dst[e]], 1);
}

__global__ __launch_bounds__(1024) void scan_kernel() {
    __shared__ int part[1024];
    const int t = threadIdx.x;
    const int CH = (NLR + 1023) / 1024;
    int start = t * CH, end = min(start + CH, NLR);
    int s = 0;
    for (int i = start; i < end; i++) s += g_cnt[i];
    part[t] = s;
    __syncthreads();
    for (int off = 1; off < 1024; off <<= 1) {
        int v = (t >= off) ? part[t - off] : 0;
        __syncthreads();
        part[t] += v;
        __syncthreads();
    }
    int run = part[t] - s;
    for (int i = start; i < end; i++) {
        g_off[i] = run; g_cur[i] = run;
        run += g_cnt[i];
    }
    if (t == 1023) g_off[NLR] = part[1023];
}

__global__ void fill_kernel(const int* __restrict__ dst) {
    int e = blockIdx.x * blockDim.x + threadIdx.x;
    if (e < ENUM) {
        int p = atomicAdd(&g_cur[dst[e]], 1);
        g_elist[p] = e;
    }
}

// =================================================================
// Warp-per-node fused segment softmax + message + b_conv + LayerNorm.
// Lane l owns channels [4l, 4l+4), head = l>>3. fp16 x_l gathers.
// =================================================================
__global__ __launch_bounds__(256) void message_ln_kernel(
    const int* __restrict__ src,
    const float* __restrict__ bconv,
    const float* __restrict__ lng, const float* __restrict__ lnb)
{
    const int node = (blockIdx.x * blockDim.x + threadIdx.x) >> 5;
    const int lane = threadIdx.x & 31;
    if (node >= NLR) return;

    const int h  = lane >> 3;
    const int c4 = lane * 4;
    const int off0 = g_off[node];
    const int deg  = g_off[node + 1] - off0;

    float4 mx = make_float4(-1e30f, -1e30f, -1e30f, -1e30f);
    for (int i = lane; i < deg; i += 32) {
        int e = __ldg(&g_elist[off0 + i]);
        float4 lg = *(const float4*)&g_logits[(size_t)e * 4];
        mx.x = fmaxf(mx.x, lg.x); mx.y = fmaxf(mx.y, lg.y);
        mx.z = fmaxf(mx.z, lg.z); mx.w = fmaxf(mx.w, lg.w);
    }
#pragma unroll
    for (int o = 16; o; o >>= 1) {
        mx.x = fmaxf(mx.x, __shfl_xor_sync(0xFFFFFFFFu, mx.x, o));
        mx.y = fmaxf(mx.y, __shfl_xor_sync(0xFFFFFFFFu, mx.y, o));
        mx.z = fmaxf(mx.z, __shfl_xor_sync(0xFFFFFFFFu, mx.z, o));
        mx.w = fmaxf(mx.w, __shfl_xor_sync(0xFFFFFFFFu, mx.w, o));
    }

    float4 sm = make_float4(0.f, 0.f, 0.f, 0.f);
    for (int i = lane; i < deg; i += 32) {
        int e = __ldg(&g_elist[off0 + i]);
        float4 lg = *(const float4*)&g_logits[(size_t)e * 4];
        sm.x += __expf(lg.x - mx.x); sm.y += __expf(lg.y - mx.y);
        sm.z += __expf(lg.z - mx.z); sm.w += __expf(lg.w - mx.w);
    }
#pragma unroll
    for (int o = 16; o; o >>= 1) {
        sm.x += __shfl_xor_sync(0xFFFFFFFFu, sm.x, o);
        sm.y += __shfl_xor_sync(0xFFFFFFFFu, sm.y, o);
        sm.z += __shfl_xor_sync(0xFFFFFFFFu, sm.z, o);
        sm.w += __shfl_xor_sync(0xFFFFFFFFu, sm.w, o);
    }

    const float m_h = (h == 0) ? mx.x : (h == 1) ? mx.y : (h == 2) ? mx.z : mx.w;
    const float s_h = (h == 0) ? sm.x : (h == 1) ? sm.y : (h == 2) ? sm.z : sm.w;
    const float inv_h = 1.f / (s_h + 1e-16f);

    float4 acc = make_float4(0.f, 0.f, 0.f, 0.f);
    for (int j = 0; j < deg; j++) {
        int e  = __ldg(&g_elist[off0 + j]);
        int sr = __ldg(&src[e]);
        float a = __expf(__ldg(&g_logits[(size_t)e * 4 + h]) - m_h);
        const __half2* xp = (const __half2*)(g_xlh + (size_t)sr * 128 + c4);
        float2 x01 = __half22float2(xp[0]);
        float2 x23 = __half22float2(xp[1]);
        acc.x = fmaf(a, x01.x, acc.x); acc.y = fmaf(a, x01.y, acc.y);
        acc.z = fmaf(a, x23.x, acc.z); acc.w = fmaf(a, x23.y, acc.w);
    }
    float4 bc = *(const float4*)&bconv[c4];
    float4 msg;
    msg.x = acc.x * inv_h + bc.x; msg.y = acc.y * inv_h + bc.y;
    msg.z = acc.z * inv_h + bc.z; msg.w = acc.w * inv_h + bc.w;

    float s1 = msg.x + msg.y + msg.z + msg.w;
    float s2 = msg.x * msg.x + msg.y * msg.y + msg.z * msg.z + msg.w * msg.w;
#pragma unroll
    for (int o = 16; o; o >>= 1) {
        s1 += __shfl_xor_sync(0xFFFFFFFFu, s1, o);
        s2 += __shfl_xor_sync(0xFFFFFFFFu, s2, o);
    }
    float mu  = s1 * (1.f / 128.f);
    float var = fmaxf(s2 * (1.f / 128.f) - mu * mu, 0.f);
    float r = rsqrtf(var + 1e-5f);

    float4 g = *(const float4*)&lng[c4];
    float4 b = *(const float4*)&lnb[c4];
    float4 o4;
    o4.x = (msg.x - mu) * r * g.x + b.x;
    o4.y = (msg.y - mu) * r * g.y + b.y;
    o4.z = (msg.z - mu) * r * g.z + b.z;
    o4.w = (msg.w - mu) * r * g.w + b.w;
    *(float4*)&g_ln[(size_t)node * 128 + c4] = o4;
}

// =================================================================
extern "C" void kernel_launch(void* const* d_in, const int* in_sizes, int n_in,
                              void* d_out, int out_size) {
    const float* left  = (const float*)d_in[0];
    const int*   eidx  = (const int*)d_in[1];
    const float* ef    = (const float*)d_in[2];
    const float* right = (const float*)d_in[3];
    const float* W_l   = (const float*)d_in[4];
    const float* b_l   = (const float*)d_in[5];
    const float* W_r   = (const float*)d_in[6];
    const float* b_r   = (const float*)d_in[7];
    const float* W_e   = (const float*)d_in[8];
    const float* att   = (const float*)d_in[9];
    const float* bconv = (const float*)d_in[10];
    const float* ln_g  = (const float*)d_in[11];
    const float* ln_b  = (const float*)d_in[12];
    const float* W1    = (const float*)d_in[13];
    const float* b1    = (const float*)d_in[14];
    const float* W2    = (const float*)d_in[15];
    const float* b2    = (const float*)d_in[16];
    float* out = (float*)d_out;

    const int* src = eidx;
    const int* dst = eidx + ENUM;

    float*  ln;  cudaGetSymbolAddress((void**)&ln,  g_ln);
    float*  h1;  cudaGetSymbolAddress((void**)&h1,  g_h1);
    __half* wTh; cudaGetSymbolAddress((void**)&wTh, g_wTh);

    cudaFuncSetAttribute(gemm128,
                         cudaFuncAttributeMaxDynamicSharedMemorySize, SMEM_GEMM);
    cudaFuncSetAttribute(gemm_dual,
                         cudaFuncAttributeMaxDynamicSharedMemorySize, SMEM_GEMM);
    cudaFuncSetAttribute(edge_logits_kernel,
                         cudaFuncAttributeMaxDynamicSharedMemorySize, SMEM_EDGE);

    const int gblk = (NLR + 127) / 128;   // 391

    // 1: one-time weight transpose + fp16 convert
    transpose5<<<96, dim3(32, 8)>>>(W_l, W_r, W_e, W1, W2);
    // 2: counter init (independent)
    zero_cnt_kernel<<<(NLR + 255) / 256, 256>>>();
    // 3: node projections (half output)
    gemm_dual<<<2 * gblk, 512, SMEM_GEMM>>>(left, wTh + WL_T, b_l,
                                            right, wTh + WR_T, b_r, NLR, gblk);
    // 4: edge logits — profiled slot
    edge_logits_kernel<<<ENUM / 128, 512, SMEM_EDGE>>>(ef, wTh + WE_T, src, dst, att);
    // 5-7: CSR build
    count_kernel<<<(ENUM + 255) / 256, 256>>>(dst);
    scan_kernel<<<1, 1024>>>();
    fill_kernel<<<(ENUM + 255) / 256, 256>>>(dst);
    // 8: warp-per-node segment softmax + message + LN
    message_ln_kernel<<<(NLR * 32 + 255) / 256, 256>>>(src, bconv, ln_g, ln_b);
    // 9-10: out MLP
    gemm128<<<gblk, 512, SMEM_GEMM>>>(ln, 128, right, 128, wTh + W1_T, 256,
                                      b1, h1, NLR, 1);
    gemm128<<<gblk, 512, SMEM_GEMM>>>(h1, 128, nullptr, 0, wTh + W2_T, 128,
                                      b2, out, NLR, 0);
}

// round 11
// speedup vs baseline: 1.5078x; 1.2176x over previous
#include <cuda_runtime.h>
#include <cuda_fp16.h>
#include <math.h>
#include <stdint.h>

#define NLR  50000
#define EMBD 128
#define ENUM 800000

#define AH_S 40   // Ash row stride (halves): conflict-free frags
#define BH_S 40   // Bsh row stride (halves)

// ---------------- device scratch (no allocations allowed) ----------------
__device__ float  g_logits[(size_t)ENUM * 4];
__device__ __half g_xlh[(size_t)NLR * EMBD];
__device__ __half g_xrh[(size_t)NLR * EMBD];
__device__ float  g_ln[(size_t)NLR * EMBD];
__device__ float  g_h1[(size_t)NLR * EMBD];
__device__ __half g_wTh[128 * 768];          // wlT|wrT|weT|w1T(128x256)|w2T
__device__ int    g_cnt[NLR];
__device__ int    g_off[NLR + 1];
__device__ int    g_cur[NLR];
__device__ int    g_elist[ENUM];

#define WL_T 0
#define WR_T 16384
#define WE_T 32768
#define W1_T 49152
#define W2_T 81920

// ---------------- helpers ----------------
__device__ __forceinline__ void mma16(float c[4], const uint32_t a[4], const uint32_t b[2]) {
    asm volatile(
        "mma.sync.aligned.m16n8k16.row.col.f32.f16.f16.f32 "
        "{%0,%1,%2,%3},{%4,%5,%6,%7},{%8,%9},{%0,%1,%2,%3};\n"
        : "+f"(c[0]), "+f"(c[1]), "+f"(c[2]), "+f"(c[3])
        : "r"(a[0]), "r"(a[1]), "r"(a[2]), "r"(a[3]), "r"(b[0]), "r"(b[1]));
}
__device__ __forceinline__ void cp16(uint32_t saddr, const void* gptr, int sz) {
    asm volatile("cp.async.cg.shared.global [%0], [%1], 16, %2;\n"
                 :: "r"(saddr), "l"(gptr), "r"(sz));
}
__device__ __forceinline__ void cp_commit() { asm volatile("cp.async.commit_group;\n"); }
__device__ __forceinline__ void cp_wait1()  { asm volatile("cp.async.wait_group 1;\n"); }
__device__ __forceinline__ void cp_wait0()  { asm volatile("cp.async.wait_group 0;\n"); }
__device__ __forceinline__ uint32_t sa(const void* p) {
    return (uint32_t)__cvta_generic_to_shared(p);
}
__device__ __forceinline__ uint32_t ldh2(const __half* p) { return *(const uint32_t*)p; }

#define ASH_BYTES (2 * 128 * AH_S * 2)   // 20480
#define BSH_BYTES (2 * 128 * BH_S * 2)   // 20480
#define SMEM_GEMM (ASH_BYTES + BSH_BYTES + 512)
#define SMEM_EDGE (ASH_BYTES + BSH_BYTES + 128 * 4 * 2 + 512)

// =================================================================
// one-time weight transpose + fp16 convert: g_wTh[n][k] = h(W[k][n])
// =================================================================
__global__ void transpose5(const float* __restrict__ Wl, const float* __restrict__ Wr,
                           const float* __restrict__ We, const float* __restrict__ W1,
                           const float* __restrict__ W2) {
    __shared__ float t[32][33];
    int b = blockIdx.x;
    const float* W; __half* out; int K;
    if      (b < 16) { W = Wl; out = g_wTh + WL_T; K = 128; }
    else if (b < 32) { W = Wr; out = g_wTh + WR_T; K = 128; b -= 16; }
    else if (b < 48) { W = We; out = g_wTh + WE_T; K = 128; b -= 32; }
    else if (b < 80) { W = W1; out = g_wTh + W1_T; K = 256; b -= 48; }
    else             { W = W2; out = g_wTh + W2_T; K = 128; b -= 80; }
    const int ktiles = K >> 5;
    const int k0 = (b % ktiles) * 32, n0 = (b / ktiles) * 32;
    const int tx = threadIdx.x, ty = threadIdx.y;
#pragma unroll
    for (int i = 0; i < 4; i++)
        t[ty + 8 * i][tx] = W[(size_t)(k0 + ty + 8 * i) * 128 + n0 + tx];
    __syncthreads();
#pragma unroll
    for (int i = 0; i < 4; i++)
        out[(size_t)(n0 + ty + 8 * i) * K + k0 + tx] = __float2half(t[tx][ty + 8 * i]);
}

// =================================================================
// GEMM body: C[M,128] = act( [A1|A2](M, K1+K2) @ BT^T + bias )
// BT: fp16 pre-transposed [128][Kb]. A: fp32 global, LDG->cvt->STS fp16.
// 512 threads, 4x4 warp grid, 32x32 warp tiles, fp16 smem operands.
// =================================================================
template <bool HALF_OUT>
__device__ __forceinline__ void gemm_body(
    const float* __restrict__ A1, int K1,
    const float* __restrict__ A2, int K2,
    const __half* __restrict__ BT, int Kb,
    const float* __restrict__ bias, float* __restrict__ C, __half* __restrict__ Ch,
    int M, int doRelu, int m0, char* smem_raw)
{
    __half (*Ash)[128][AH_S] = (__half(*)[128][AH_S])smem_raw;
    __half (*Bsh)[128][BH_S] = (__half(*)[128][BH_S])(smem_raw + ASH_BYTES);
    float* bias_s            = (float*)(smem_raw + ASH_BYTES + BSH_BYTES);

    const int tid = threadIdx.x;
    if (tid < 128) bias_s[tid] = bias[tid];

    const int warp = tid >> 5, lane = tid & 31;
    const int wm = warp & 3, wn = warp >> 2;
    const int grp = lane >> 2, tg = lane & 3;

    const int nch1 = K1 >> 5;
    const int nch  = Kb >> 5;

    const int ar0 = tid >> 3, ac = (tid & 7) * 4;

    auto ldgA = [&](int c, float4& a0, float4& a1) {
        const float* A; int K, ka;
        if (c < nch1) { A = A1; K = K1; ka = c * 32; }
        else          { A = A2; K = K2; ka = c * 32 - K1; }
        int g0 = m0 + ar0, g1 = m0 + ar0 + 64;
        a0 = (g0 < M) ? *(const float4*)(A + (size_t)g0 * K + ka + ac)
                      : make_float4(0.f, 0.f, 0.f, 0.f);
        a1 = (g1 < M) ? *(const float4*)(A + (size_t)g1 * K + ka + ac)
                      : make_float4(0.f, 0.f, 0.f, 0.f);
    };
    auto stsA = [&](int buf, const float4& a0, const float4& a1) {
        __half2 h0 = __floats2half2_rn(a0.x, a0.y), h1 = __floats2half2_rn(a0.z, a0.w);
        *(uint2*)&Ash[buf][ar0][ac]      = make_uint2(*(uint32_t*)&h0, *(uint32_t*)&h1);
        __half2 h2 = __floats2half2_rn(a1.x, a1.y), h3 = __floats2half2_rn(a1.z, a1.w);
        *(uint2*)&Ash[buf][ar0 + 64][ac] = make_uint2(*(uint32_t*)&h2, *(uint32_t*)&h3);
    };
    const int br = tid >> 2, bu = (tid & 3) * 8;
    auto stageB = [&](int c, int buf) {
        cp16(sa(&Bsh[buf][br][bu]), BT + (size_t)br * Kb + c * 32 + bu, 16);
        cp_commit();
    };

    float acc[2][4][4];
#pragma unroll
    for (int a = 0; a < 2; a++)
#pragma unroll
        for (int b = 0; b < 4; b++)
#pragma unroll
            for (int k = 0; k < 4; k++) acc[a][b][k] = 0.f;

    float4 a0, a1;
    ldgA(0, a0, a1);
    stageB(0, 0);

    for (int c = 0; c < nch; c++) {
        const int buf = c & 1;
        __syncthreads();
        stsA(buf, a0, a1);
        if (c + 1 < nch) {
            stageB(c + 1, buf ^ 1);
            ldgA(c + 1, a0, a1);
            cp_wait1();
        } else {
            cp_wait0();
        }
        __syncthreads();

#pragma unroll
        for (int ks = 0; ks < 2; ks++) {
            const int kb = ks * 16;
            uint32_t af[2][4];
#pragma unroll
            for (int mt = 0; mt < 2; mt++) {
                int r0 = wm * 32 + mt * 16 + grp;
                af[mt][0] = ldh2(&Ash[buf][r0][kb + 2 * tg]);
                af[mt][1] = ldh2(&Ash[buf][r0 + 8][kb + 2 * tg]);
                af[mt][2] = ldh2(&Ash[buf][r0][kb + 2 * tg + 8]);
                af[mt][3] = ldh2(&Ash[buf][r0 + 8][kb + 2 * tg + 8]);
            }
#pragma unroll
            for (int nt = 0; nt < 4; nt++) {
                int cc = wn * 32 + nt * 8 + grp;
                uint32_t bf[2];
                bf[0] = ldh2(&Bsh[buf][cc][kb + 2 * tg]);
                bf[1] = ldh2(&Bsh[buf][cc][kb + 2 * tg + 8]);
                mma16(acc[0][nt], af[0], bf);
                mma16(acc[1][nt], af[1], bf);
            }
        }
    }

#pragma unroll
    for (int mt = 0; mt < 2; mt++) {
#pragma unroll
        for (int half = 0; half < 2; half++) {
            int grow = m0 + wm * 32 + mt * 16 + half * 8 + grp;
            if (grow < M) {
#pragma unroll
                for (int nt = 0; nt < 4; nt++) {
                    int cc = wn * 32 + nt * 8 + tg * 2;
                    float v0 = acc[mt][nt][half * 2 + 0] + bias_s[cc];
                    float v1 = acc[mt][nt][half * 2 + 1] + bias_s[cc + 1];
                    if (doRelu) { v0 = fmaxf(v0, 0.f); v1 = fmaxf(v1, 0.f); }
                    if (HALF_OUT) {
                        __half2 h = __floats2half2_rn(v0, v1);
                        *(__half2*)(Ch + (size_t)grow * 128 + cc) = h;
                    } else {
                        float2 o; o.x = v0; o.y = v1;
                        *(float2*)(C + (size_t)grow * 128 + cc) = o;
                    }
                }
            }
        }
    }
}

__global__ __launch_bounds__(512, 2) void gemm128(
    const float* __restrict__ A1, int K1,
    const float* __restrict__ A2, int K2,
    const __half* __restrict__ BT, int Kb,
    const float* __restrict__ bias, float* __restrict__ C, int M, int doRelu)
{
    extern __shared__ char smem_raw[];
    gemm_body<false>(A1, K1, A2, K2, BT, Kb, bias, C, nullptr, M, doRelu,
                     blockIdx.x * 128, smem_raw);
}

// node projections merged, half output to g_xlh / g_xrh
__global__ __launch_bounds__(512, 2) void gemm_dual(
    const float* __restrict__ Aa, const __half* __restrict__ BTa,
    const float* __restrict__ ba,
    const float* __restrict__ Ab, const __half* __restrict__ BTb,
    const float* __restrict__ bb,
    int M, int half)
{
    extern __shared__ char smem_raw[];
    if (blockIdx.x < half)
        gemm_body<true>(Aa, 128, nullptr, 0, BTa, 128, ba, nullptr, g_xlh, M, 0,
                        blockIdx.x * 128, smem_raw);
    else
        gemm_body<true>(Ab, 128, nullptr, 0, BTb, 128, bb, nullptr, g_xrh, M, 0,
                        (blockIdx.x - half) * 128, smem_raw);
}

// =================================================================
// Fused edge kernel: eproj = EF @ W_e (fp16 smem operands),
// z = leakyrelu(eproj + x_l[src] + x_r[dst], 0.2),
// logits[e,h] = z_h . att_h  -> g_logits[E][4]; head = wn.
// =================================================================
__global__ __launch_bounds__(512, 2) void edge_logits_kernel(
    const float* __restrict__ EF, const __half* __restrict__ WeT,
    const int* __restrict__ src, const int* __restrict__ dst,
    const float* __restrict__ att)
{
    extern __shared__ char smem_raw[];
    __half (*Ash)[128][AH_S] = (__half(*)[128][AH_S])smem_raw;
    __half (*Bsh)[128][BH_S] = (__half(*)[128][BH_S])(smem_raw + ASH_BYTES);
    int*   src_s = (int*)(smem_raw + ASH_BYTES + BSH_BYTES);
    int*   dst_s = src_s + 128;
    float* att_s = (float*)(dst_s + 128);

    const int tid = threadIdx.x;
    const int e0  = blockIdx.x * 128;

    if (tid < 128) {
        src_s[tid] = src[e0 + tid];
        dst_s[tid] = dst[e0 + tid];
        att_s[tid] = att[tid];
    }

    const int warp = tid >> 5, lane = tid & 31;
    const int wm = warp & 3, wn = warp >> 2;
    const int grp = lane >> 2, tg = lane & 3;

    const int ar0 = tid >> 3, ac = (tid & 7) * 4;
    const int br = tid >> 2, bu = (tid & 3) * 8;

    auto ldgA = [&](int c, float4& a0, float4& a1) {
        const int ka = c * 32;
        a0 = *(const float4*)(EF + (size_t)(e0 + ar0) * 128 + ka + ac);
        a1 = *(const float4*)(EF + (size_t)(e0 + ar0 + 64) * 128 + ka + ac);
    };
    auto stsA = [&](int buf, const float4& a0, const float4& a1) {
        __half2 h0 = __floats2half2_rn(a0.x, a0.y), h1 = __floats2half2_rn(a0.z, a0.w);
        *(uint2*)&Ash[buf][ar0][ac]      = make_uint2(*(uint32_t*)&h0, *(uint32_t*)&h1);
        __half2 h2 = __floats2half2_rn(a1.x, a1.y), h3 = __floats2half2_rn(a1.z, a1.w);
        *(uint2*)&Ash[buf][ar0 + 64][ac] = make_uint2(*(uint32_t*)&h2, *(uint32_t*)&h3);
    };
    auto stageB = [&](int c, int buf) {
        cp16(sa(&Bsh[buf][br][bu]), WeT + (size_t)br * 128 + c * 32 + bu, 16);
        cp_commit();
    };

    float acc[2][4][4];
#pragma unroll
    for (int a = 0; a < 2; a++)
#pragma unroll
        for (int b = 0; b < 4; b++)
#pragma unroll
            for (int k = 0; k < 4; k++) acc[a][b][k] = 0.f;

    float4 a0, a1;
    ldgA(0, a0, a1);
    stageB(0, 0);

#pragma unroll
    for (int c = 0; c < 4; c++) {
        const int buf = c & 1;
        __syncthreads();
        stsA(buf, a0, a1);
        if (c + 1 < 4) {
            stageB(c + 1, buf ^ 1);
            ldgA(c + 1, a0, a1);
            cp_wait1();
        } else {
            cp_wait0();
        }
        __syncthreads();

#pragma unroll
        for (int ks = 0; ks < 2; ks++) {
            const int kb = ks * 16;
            uint32_t af[2][4];
#pragma unroll
            for (int mt = 0; mt < 2; mt++) {
                int r0 = wm * 32 + mt * 16 + grp;
                af[mt][0] = ldh2(&Ash[buf][r0][kb + 2 * tg]);
                af[mt][1] = ldh2(&Ash[buf][r0 + 8][kb + 2 * tg]);
                af[mt][2] = ldh2(&Ash[buf][r0][kb + 2 * tg + 8]);
                af[mt][3] = ldh2(&Ash[buf][r0 + 8][kb + 2 * tg + 8]);
            }
#pragma unroll
            for (int nt = 0; nt < 4; nt++) {
                int cc = wn * 32 + nt * 8 + grp;
                uint32_t bf[2];
                bf[0] = ldh2(&Bsh[buf][cc][kb + 2 * tg]);
                bf[1] = ldh2(&Bsh[buf][cc][kb + 2 * tg + 8]);
                mma16(acc[0][nt], af[0], bf);
                mma16(acc[1][nt], af[1], bf);
            }
        }
    }

    // epilogue: fp16 gathers of x_l[src], x_r[dst]; head = wn
#pragma unroll
    for (int mt = 0; mt < 2; mt++) {
#pragma unroll
        for (int half = 0; half < 2; half++) {
            int row = wm * 32 + mt * 16 + half * 8 + grp;
            const __half* xl = g_xlh + (size_t)src_s[row] * 128;
            const __half* xr = g_xrh + (size_t)dst_s[row] * 128;
            float partial = 0.f;
#pragma unroll
            for (int nt = 0; nt < 4; nt++) {
                int col = wn * 32 + nt * 8 + tg * 2;
                float2 a = __half22float2(*(const __half2*)(xl + col));
                float2 b = __half22float2(*(const __half2*)(xr + col));
                float z0 = acc[mt][nt][half * 2 + 0] + a.x + b.x;
                float z1 = acc[mt][nt][half * 2 + 1] + a.y + b.y;
                z0 = (z0 > 0.f) ? z0 : 0.2f * z0;
                z1 = (z1 > 0.f) ? z1 : 0.2f * z1;
                partial += z0 * att_s[col] + z1 * att_s[col + 1];
            }
            partial += __shfl_xor_sync(0xFFFFFFFFu, partial, 1);
            partial += __shfl_xor_sync(0xFFFFFFFFu, partial, 2);
            if (tg == 0)
                g_logits[(size_t)(e0 + row) * 4 + wn] = partial;
        }
    }
}

// ---------------- CSR build ----------------
__global__ void count_kernel(const int* __restrict__ dst) {
    int e = blockIdx.x * blockDim.x + threadIdx.x;
    if (e < ENUM) atomicAdd(&g_cnt[dst[e]], 1);
}

__global__ __launch_bounds__(1024) void scan_kernel() {
    __shared__ int part[1024];
    const int t = threadIdx.x;
    const int CH = (NLR + 1023) / 1024;
    int start = t * CH, end = min(start + CH, NLR);
    int s = 0;
    for (int i = start; i < end; i++) s += g_cnt[i];
    part[t] = s;
    __syncthreads();
    for (int off = 1; off < 1024; off <<= 1) {
        int v = (t >= off) ? part[t - off] : 0;
        __syncthreads();
        part[t] += v;
        __syncthreads();
    }
    int run = part[t] - s;
    for (int i = start; i < end; i++) {
        g_off[i] = run; g_cur[i] = run;
        run += g_cnt[i];
    }
    if (t == 1023) g_off[NLR] = part[1023];
}

__global__ void fill_kernel(const int* __restrict__ dst) {
    int e = blockIdx.x * blockDim.x + threadIdx.x;
    if (e < ENUM) {
        int p = atomicAdd(&g_cur[dst[e]], 1);
        g_elist[p] = e;
    }
}

// =================================================================
// Warp-per-node fused segment softmax + message + b_conv + LayerNorm.
// Lane l owns channels [4l, 4l+4), head = l>>3. fp16 x_l gathers.
// =================================================================
__global__ __launch_bounds__(256) void message_ln_kernel(
    const int* __restrict__ src,
    const float* __restrict__ bconv,
    const float* __restrict__ lng, const float* __restrict__ lnb)
{
    const int node = (blockIdx.x * blockDim.x + threadIdx.x) >> 5;
    const int lane = threadIdx.x & 31;
    if (node >= NLR) return;

    const int h  = lane >> 3;
    const int c4 = lane * 4;
    const int off0 = g_off[node];
    const int deg  = g_off[node + 1] - off0;

    float4 mx = make_float4(-1e30f, -1e30f, -1e30f, -1e30f);
    for (int i = lane; i < deg; i += 32) {
        int e = __ldg(&g_elist[off0 + i]);
        float4 lg = *(const float4*)&g_logits[(size_t)e * 4];
        mx.x = fmaxf(mx.x, lg.x); mx.y = fmaxf(mx.y, lg.y);
        mx.z = fmaxf(mx.z, lg.z); mx.w = fmaxf(mx.w, lg.w);
    }
#pragma unroll
    for (int o = 16; o; o >>= 1) {
        mx.x = fmaxf(mx.x, __shfl_xor_sync(0xFFFFFFFFu, mx.x, o));
        mx.y = fmaxf(mx.y, __shfl_xor_sync(0xFFFFFFFFu, mx.y, o));
        mx.z = fmaxf(mx.z, __shfl_xor_sync(0xFFFFFFFFu, mx.z, o));
        mx.w = fmaxf(mx.w, __shfl_xor_sync(0xFFFFFFFFu, mx.w, o));
    }

    float4 sm = make_float4(0.f, 0.f, 0.f, 0.f);
    for (int i = lane; i < deg; i += 32) {
        int e = __ldg(&g_elist[off0 + i]);
        float4 lg = *(const float4*)&g_logits[(size_t)e * 4];
        sm.x += __expf(lg.x - mx.x); sm.y += __expf(lg.y - mx.y);
        sm.z += __expf(lg.z - mx.z); sm.w += __expf(lg.w - mx.w);
    }
#pragma unroll
    for (int o = 16; o; o >>= 1) {
        sm.x += __shfl_xor_sync(0xFFFFFFFFu, sm.x, o);
        sm.y += __shfl_xor_sync(0xFFFFFFFFu, sm.y, o);
        sm.z += __shfl_xor_sync(0xFFFFFFFFu, sm.z, o);
        sm.w += __shfl_xor_sync(0xFFFFFFFFu, sm.w, o);
    }

    const float m_h = (h == 0) ? mx.x : (h == 1) ? mx.y : (h == 2) ? mx.z : mx.w;
    const float s_h = (h == 0) ? sm.x : (h == 1) ? sm.y : (h == 2) ? sm.z : sm.w;
    const float inv_h = 1.f / (s_h + 1e-16f);

    float4 acc = make_float4(0.f, 0.f, 0.f, 0.f);
    for (int j = 0; j < deg; j++) {
        int e  = __ldg(&g_elist[off0 + j]);
        int sr = __ldg(&src[e]);
        float a = __expf(__ldg(&g_logits[(size_t)e * 4 + h]) - m_h);
        const __half2* xp = (const __half2*)(g_xlh + (size_t)sr * 128 + c4);
        float2 x01 = __half22float2(xp[0]);
        float2 x23 = __half22float2(xp[1]);
        acc.x = fmaf(a, x01.x, acc.x); acc.y = fmaf(a, x01.y, acc.y);
        acc.z = fmaf(a, x23.x, acc.z); acc.w = fmaf(a, x23.y, acc.w);
    }
    float4 bc = *(const float4*)&bconv[c4];
    float4 msg;
    msg.x = acc.x * inv_h + bc.x; msg.y = acc.y * inv_h + bc.y;
    msg.z = acc.z * inv_h + bc.z; msg.w = acc.w * inv_h + bc.w;

    float s1 = msg.x + msg.y + msg.z + msg.w;
    float s2 = msg.x * msg.x + msg.y * msg.y + msg.z * msg.z + msg.w * msg.w;
#pragma unroll
    for (int o = 16; o; o >>= 1) {
        s1 += __shfl_xor_sync(0xFFFFFFFFu, s1, o);
        s2 += __shfl_xor_sync(0xFFFFFFFFu, s2, o);
    }
    float mu  = s1 * (1.f / 128.f);
    float var = fmaxf(s2 * (1.f / 128.f) - mu * mu, 0.f);
    float r = rsqrtf(var + 1e-5f);

    float4 g = *(const float4*)&lng[c4];
    float4 b = *(const float4*)&lnb[c4];
    float4 o4;
    o4.x = (msg.x - mu) * r * g.x + b.x;
    o4.y = (msg.y - mu) * r * g.y + b.y;
    o4.z = (msg.z - mu) * r * g.z + b.z;
    o4.w = (msg.w - mu) * r * g.w + b.w;
    *(float4*)&g_ln[(size_t)node * 128 + c4] = o4;
}

// =================================================================
extern "C" void kernel_launch(void* const* d_in, const int* in_sizes, int n_in,
                              void* d_out, int out_size) {
    const float* left  = (const float*)d_in[0];
    const int*   eidx  = (const int*)d_in[1];
    const float* ef    = (const float*)d_in[2];
    const float* right = (const float*)d_in[3];
    const float* W_l   = (const float*)d_in[4];
    const float* b_l   = (const float*)d_in[5];
    const float* W_r   = (const float*)d_in[6];
    const float* b_r   = (const float*)d_in[7];
    const float* W_e   = (const float*)d_in[8];
    const float* att   = (const float*)d_in[9];
    const float* bconv = (const float*)d_in[10];
    const float* ln_g  = (const float*)d_in[11];
    const float* ln_b  = (const float*)d_in[12];
    const float* W1    = (const float*)d_in[13];
    const float* b1    = (const float*)d_in[14];
    const float* W2    = (const float*)d_in[15];
    const float* b2    = (const float*)d_in[16];
    float* out = (float*)d_out;

    const int* src = eidx;
    const int* dst = eidx + ENUM;

    float*  ln;  cudaGetSymbolAddress((void**)&ln,  g_ln);
    float*  h1;  cudaGetSymbolAddress((void**)&h1,  g_h1);
    __half* wTh; cudaGetSymbolAddress((void**)&wTh, g_wTh);
    int*    cnt; cudaGetSymbolAddress((void**)&cnt, g_cnt);

    cudaFuncSetAttribute(gemm128,
                         cudaFuncAttributeMaxDynamicSharedMemorySize, SMEM_GEMM);
    cudaFuncSetAttribute(gemm_dual,
                         cudaFuncAttributeMaxDynamicSharedMemorySize, SMEM_GEMM);
    cudaFuncSetAttribute(edge_logits_kernel,
                         cudaFuncAttributeMaxDynamicSharedMemorySize, SMEM_EDGE);

    const int gblk = (NLR + 127) / 128;   // 391

    // side stream for the CSR branch (independent of the GEMM chain)
    cudaStream_t s2;
    cudaStreamCreateWithFlags(&s2, cudaStreamNonBlocking);
    cudaEvent_t evFork, evJoin;
    cudaEventCreateWithFlags(&evFork, cudaEventDisableTiming);
    cudaEventCreateWithFlags(&evJoin, cudaEventDisableTiming);

    // fork: s2 depends on capture-stream start
    cudaEventRecord(evFork, 0);
    cudaStreamWaitEvent(s2, evFork, 0);

    // CSR branch on s2: memset + count + scan + fill
    cudaMemsetAsync(cnt, 0, NLR * sizeof(int), s2);

    // main chain, interleaved so edge_logits is kernel launch #4:
    transpose5<<<96, dim3(32, 8)>>>(W_l, W_r, W_e, W1, W2);                  // k1
    count_kernel<<<(ENUM + 255) / 256, 256, 0, s2>>>(dst);                   // k2
    gemm_dual<<<2 * gblk, 512, SMEM_GEMM>>>(left, wTh + WL_T, b_l,
                                            right, wTh + WR_T, b_r,
                                            NLR, gblk);                      // k3
    edge_logits_kernel<<<ENUM / 128, 512, SMEM_EDGE>>>(ef, wTh + WE_T,
                                                       src, dst, att);       // k4 (profiled)
    scan_kernel<<<1, 1024, 0, s2>>>();                                       // k5
    fill_kernel<<<(ENUM + 255) / 256, 256, 0, s2>>>(dst);                    // k6

    // join: main waits for CSR branch
    cudaEventRecord(evJoin, s2);
    cudaStreamWaitEvent(0, evJoin, 0);

    // message + MLP on main
    message_ln_kernel<<<(NLR * 32 + 255) / 256, 256>>>(src, bconv, ln_g, ln_b); // k7
    gemm128<<<gblk, 512, SMEM_GEMM>>>(ln, 128, right, 128, wTh + W1_T, 256,
                                      b1, h1, NLR, 1);                       // k8
    gemm128<<<gblk, 512, SMEM_GEMM>>>(h1, 128, nullptr, 0, wTh + W2_T, 128,
                                      b2, out, NLR, 0);                      // k9
}

// round 12
// speedup vs baseline: 1.7195x; 1.1404x over previous
#include <cuda_runtime.h>
#include <cuda_fp16.h>
#include <math.h>
#include <stdint.h>

#define NLR  50000
#define EMBD 128
#define ENUM 800000

#define AH_S 40   // gemm smem row stride (halves) = 80B
#define BH_S 40

// ---------------- device scratch (no allocations allowed) ----------------
__device__ float  g_logits[(size_t)ENUM * 4];
__device__ __half g_xlh[(size_t)NLR * EMBD];
__device__ __half g_xrh[(size_t)NLR * EMBD];
__device__ float  g_ln[(size_t)NLR * EMBD];
__device__ float  g_h1[(size_t)NLR * EMBD];
__device__ __half g_wTh[128 * 768];          // wlT|wrT|weT|w1T(128x256)|w2T
__device__ int    g_cnt[NLR];
__device__ int    g_off[NLR + 1];
__device__ int    g_cur[NLR];
__device__ int    g_elist[ENUM];

#define WL_T 0
#define WR_T 16384
#define WE_T 32768
#define W1_T 49152
#define W2_T 81920

// ---------------- helpers ----------------
__device__ __forceinline__ void mma16(float c[4], const uint32_t a[4], const uint32_t b[2]) {
    asm volatile(
        "mma.sync.aligned.m16n8k16.row.col.f32.f16.f16.f32 "
        "{%0,%1,%2,%3},{%4,%5,%6,%7},{%8,%9},{%0,%1,%2,%3};\n"
        : "+f"(c[0]), "+f"(c[1]), "+f"(c[2]), "+f"(c[3])
        : "r"(a[0]), "r"(a[1]), "r"(a[2]), "r"(a[3]), "r"(b[0]), "r"(b[1]));
}
__device__ __forceinline__ void ldm4(uint32_t* r, uint32_t addr) {
    asm volatile("ldmatrix.sync.aligned.m8n8.x4.shared.b16 {%0,%1,%2,%3}, [%4];"
                 : "=r"(r[0]), "=r"(r[1]), "=r"(r[2]), "=r"(r[3]) : "r"(addr));
}
__device__ __forceinline__ void cp16(uint32_t saddr, const void* gptr, int sz) {
    asm volatile("cp.async.cg.shared.global [%0], [%1], 16, %2;\n"
                 :: "r"(saddr), "l"(gptr), "r"(sz));
}
__device__ __forceinline__ void cp_commit() { asm volatile("cp.async.commit_group;\n"); }
__device__ __forceinline__ void cp_wait1()  { asm volatile("cp.async.wait_group 1;\n"); }
__device__ __forceinline__ void cp_wait0()  { asm volatile("cp.async.wait_group 0;\n"); }
__device__ __forceinline__ uint32_t sa(const void* p) {
    return (uint32_t)__cvta_generic_to_shared(p);
}
__device__ __forceinline__ uint32_t ldh2(const __half* p) { return *(const uint32_t*)p; }

#define ASH_BYTES (2 * 128 * AH_S * 2)   // 20480
#define BSH_BYTES (2 * 128 * BH_S * 2)   // 20480
#define SMEM_GEMM (ASH_BYTES + BSH_BYTES + 512)

// ---- edge kernel smem layout (v12) ----
#define EASH  0                     // 2 x 128 x 40 halves  (20480 B)
#define EBSH  20480                 // 2 x 128 x 40 halves  (20480 B)
#define EGATH 40960                 // 256 rows x 136 halves (69632 B)
#define EATT  110592                // 128 floats
#define ESRC  111104                // 128 ints
#define EDST  111616                // 128 ints
#define SMEM_EDGE2 112128
#define GSTR  136                   // gather row stride in halves (272 B)

// =================================================================
// one-time weight transpose + fp16 convert: g_wTh[n][k] = h(W[k][n])
// =================================================================
__global__ void transpose5(const float* __restrict__ Wl, const float* __restrict__ Wr,
                           const float* __restrict__ We, const float* __restrict__ W1,
                           const float* __restrict__ W2) {
    __shared__ float t[32][33];
    int b = blockIdx.x;
    const float* W; __half* out; int K;
    if      (b < 16) { W = Wl; out = g_wTh + WL_T; K = 128; }
    else if (b < 32) { W = Wr; out = g_wTh + WR_T; K = 128; b -= 16; }
    else if (b < 48) { W = We; out = g_wTh + WE_T; K = 128; b -= 32; }
    else if (b < 80) { W = W1; out = g_wTh + W1_T; K = 256; b -= 48; }
    else             { W = W2; out = g_wTh + W2_T; K = 128; b -= 80; }
    const int ktiles = K >> 5;
    const int k0 = (b % ktiles) * 32, n0 = (b / ktiles) * 32;
    const int tx = threadIdx.x, ty = threadIdx.y;
#pragma unroll
    for (int i = 0; i < 4; i++)
        t[ty + 8 * i][tx] = W[(size_t)(k0 + ty + 8 * i) * 128 + n0 + tx];
    __syncthreads();
#pragma unroll
    for (int i = 0; i < 4; i++)
        out[(size_t)(n0 + ty + 8 * i) * K + k0 + tx] = __float2half(t[tx][ty + 8 * i]);
}

// =================================================================
// mma.sync GEMM body (node projections + MLP), unchanged from R11
// =================================================================
template <bool HALF_OUT>
__device__ __forceinline__ void gemm_body(
    const float* __restrict__ A1, int K1,
    const float* __restrict__ A2, int K2,
    const __half* __restrict__ BT, int Kb,
    const float* __restrict__ bias, float* __restrict__ C, __half* __restrict__ Ch,
    int M, int doRelu, int m0, char* smem_raw)
{
    __half (*Ash)[128][AH_S] = (__half(*)[128][AH_S])smem_raw;
    __half (*Bsh)[128][BH_S] = (__half(*)[128][BH_S])(smem_raw + ASH_BYTES);
    float* bias_s            = (float*)(smem_raw + ASH_BYTES + BSH_BYTES);

    const int tid = threadIdx.x;
    if (tid < 128) bias_s[tid] = bias[tid];

    const int warp = tid >> 5, lane = tid & 31;
    const int wm = warp & 3, wn = warp >> 2;
    const int grp = lane >> 2, tg = lane & 3;

    const int nch1 = K1 >> 5;
    const int nch  = Kb >> 5;

    const int ar0 = tid >> 3, ac = (tid & 7) * 4;

    auto ldgA = [&](int c, float4& a0, float4& a1) {
        const float* A; int K, ka;
        if (c < nch1) { A = A1; K = K1; ka = c * 32; }
        else          { A = A2; K = K2; ka = c * 32 - K1; }
        int g0 = m0 + ar0, g1 = m0 + ar0 + 64;
        a0 = (g0 < M) ? *(const float4*)(A + (size_t)g0 * K + ka + ac)
                      : make_float4(0.f, 0.f, 0.f, 0.f);
        a1 = (g1 < M) ? *(const float4*)(A + (size_t)g1 * K + ka + ac)
                      : make_float4(0.f, 0.f, 0.f, 0.f);
    };
    auto stsA = [&](int buf, const float4& a0, const float4& a1) {
        __half2 h0 = __floats2half2_rn(a0.x, a0.y), h1 = __floats2half2_rn(a0.z, a0.w);
        *(uint2*)&Ash[buf][ar0][ac]      = make_uint2(*(uint32_t*)&h0, *(uint32_t*)&h1);
        __half2 h2 = __floats2half2_rn(a1.x, a1.y), h3 = __floats2half2_rn(a1.z, a1.w);
        *(uint2*)&Ash[buf][ar0 + 64][ac] = make_uint2(*(uint32_t*)&h2, *(uint32_t*)&h3);
    };
    const int br = tid >> 2, bu = (tid & 3) * 8;
    auto stageB = [&](int c, int buf) {
        cp16(sa(&Bsh[buf][br][bu]), BT + (size_t)br * Kb + c * 32 + bu, 16);
        cp_commit();
    };

    float acc[2][4][4];
#pragma unroll
    for (int a = 0; a < 2; a++)
#pragma unroll
        for (int b = 0; b < 4; b++)
#pragma unroll
            for (int k = 0; k < 4; k++) acc[a][b][k] = 0.f;

    float4 a0, a1;
    ldgA(0, a0, a1);
    stageB(0, 0);

    for (int c = 0; c < nch; c++) {
        const int buf = c & 1;
        __syncthreads();
        stsA(buf, a0, a1);
        if (c + 1 < nch) {
            stageB(c + 1, buf ^ 1);
            ldgA(c + 1, a0, a1);
            cp_wait1();
        } else {
            cp_wait0();
        }
        __syncthreads();

#pragma unroll
        for (int ks = 0; ks < 2; ks++) {
            const int kb = ks * 16;
            uint32_t af[2][4];
#pragma unroll
            for (int mt = 0; mt < 2; mt++) {
                int r0 = wm * 32 + mt * 16 + grp;
                af[mt][0] = ldh2(&Ash[buf][r0][kb + 2 * tg]);
                af[mt][1] = ldh2(&Ash[buf][r0 + 8][kb + 2 * tg]);
                af[mt][2] = ldh2(&Ash[buf][r0][kb + 2 * tg + 8]);
                af[mt][3] = ldh2(&Ash[buf][r0 + 8][kb + 2 * tg + 8]);
            }
#pragma unroll
            for (int nt = 0; nt < 4; nt++) {
                int cc = wn * 32 + nt * 8 + grp;
                uint32_t bf[2];
                bf[0] = ldh2(&Bsh[buf][cc][kb + 2 * tg]);
                bf[1] = ldh2(&Bsh[buf][cc][kb + 2 * tg + 8]);
                mma16(acc[0][nt], af[0], bf);
                mma16(acc[1][nt], af[1], bf);
            }
        }
    }

#pragma unroll
    for (int mt = 0; mt < 2; mt++) {
#pragma unroll
        for (int half = 0; half < 2; half++) {
            int grow = m0 + wm * 32 + mt * 16 + half * 8 + grp;
            if (grow < M) {
#pragma unroll
                for (int nt = 0; nt < 4; nt++) {
                    int cc = wn * 32 + nt * 8 + tg * 2;
                    float v0 = acc[mt][nt][half * 2 + 0] + bias_s[cc];
                    float v1 = acc[mt][nt][half * 2 + 1] + bias_s[cc + 1];
                    if (doRelu) { v0 = fmaxf(v0, 0.f); v1 = fmaxf(v1, 0.f); }
                    if (HALF_OUT) {
                        __half2 h = __floats2half2_rn(v0, v1);
                        *(__half2*)(Ch + (size_t)grow * 128 + cc) = h;
                    } else {
                        float2 o; o.x = v0; o.y = v1;
                        *(float2*)(C + (size_t)grow * 128 + cc) = o;
                    }
                }
            }
        }
    }
}

__global__ __launch_bounds__(512, 2) void gemm128(
    const float* __restrict__ A1, int K1,
    const float* __restrict__ A2, int K2,
    const __half* __restrict__ BT, int Kb,
    const float* __restrict__ bias, float* __restrict__ C, int M, int doRelu)
{
    extern __shared__ char smem_raw[];
    gemm_body<false>(A1, K1, A2, K2, BT, Kb, bias, C, nullptr, M, doRelu,
                     blockIdx.x * 128, smem_raw);
}

__global__ __launch_bounds__(512, 2) void gemm_dual(
    const float* __restrict__ Aa, const __half* __restrict__ BTa,
    const float* __restrict__ ba,
    const float* __restrict__ Ab, const __half* __restrict__ BTb,
    const float* __restrict__ bb,
    int M, int half)
{
    extern __shared__ char smem_raw[];
    if (blockIdx.x < half)
        gemm_body<true>(Aa, 128, nullptr, 0, BTa, 128, ba, nullptr, g_xlh, M, 0,
                        blockIdx.x * 128, smem_raw);
    else
        gemm_body<true>(Ab, 128, nullptr, 0, BTb, 128, bb, nullptr, g_xrh, M, 0,
                        (blockIdx.x - half) * 128, smem_raw);
}

// =================================================================
// Edge kernel v12: ldmatrix fragments, single sync/chunk, cp.async
// smem-staged xl/xr gathers (epilogue = conflict-free LDS).
// =================================================================
__global__ __launch_bounds__(512, 2) void edge_logits_kernel(
    const float* __restrict__ EF, const __half* __restrict__ WeT,
    const int* __restrict__ src, const int* __restrict__ dst,
    const float* __restrict__ att)
{
    extern __shared__ char smem[];
    const uint32_t sb = sa(smem);
    float* att_s = (float*)(smem + EATT);
    int*   src_s = (int*)(smem + ESRC);
    int*   dst_s = (int*)(smem + EDST);
    const __half* gath = (const __half*)(smem + EGATH);

    const int tid = threadIdx.x;
    const int e0  = blockIdx.x * 128;
    const int warp = tid >> 5, lane = tid & 31;
    const int wm = warp & 3, wn = warp >> 2;
    const int grp = lane >> 2, tg = lane & 3;

    if (tid < 128) {
        src_s[tid] = src[e0 + tid];
        dst_s[tid] = dst[e0 + tid];
        att_s[tid] = att[tid];
    }

    // ---- A staging (LDG fp32 -> cvt -> STS fp16) ----
    const int ar0 = tid >> 3, ac = (tid & 7) * 4;
    float4 a0, a1;
    auto ldgA = [&](int c) {
        const int ka = c * 32;
        a0 = *(const float4*)(EF + (size_t)(e0 + ar0) * 128 + ka + ac);
        a1 = *(const float4*)(EF + (size_t)(e0 + ar0 + 64) * 128 + ka + ac);
    };
    auto stsA = [&](int buf) {
        char* base = smem + EASH + buf * 10240;
        __half2 h0 = __floats2half2_rn(a0.x, a0.y), h1 = __floats2half2_rn(a0.z, a0.w);
        *(uint2*)(base + ar0 * 80 + ac * 2) = make_uint2(*(uint32_t*)&h0, *(uint32_t*)&h1);
        __half2 h2 = __floats2half2_rn(a1.x, a1.y), h3 = __floats2half2_rn(a1.z, a1.w);
        *(uint2*)(base + (ar0 + 64) * 80 + ac * 2) = make_uint2(*(uint32_t*)&h2, *(uint32_t*)&h3);
    };
    const int br = tid >> 2, bu = (tid & 3) * 8;
    auto stageB = [&](int c, int buf) {
        cp16(sb + EBSH + buf * 10240 + br * 80 + bu * 2,
             WeT + (size_t)br * 128 + c * 32 + bu, 16);
        cp_commit();
    };

    // ---- ldmatrix lane address parts ----
    const uint32_t aOff = (uint32_t)(wm * 32 + (lane & 15)) * 80 + (uint32_t)((lane >> 4) << 3) * 2;
    const uint32_t bOff = (uint32_t)(wn * 32 + (lane & 7) + ((lane >> 4) << 3)) * 80
                        + (uint32_t)(((lane >> 3) & 1) << 3) * 2;

    float acc[2][4][4];
#pragma unroll
    for (int a = 0; a < 2; a++)
#pragma unroll
        for (int b = 0; b < 4; b++)
#pragma unroll
            for (int k = 0; k < 4; k++) acc[a][b][k] = 0.f;

    auto compute = [&](int buf) {
        const uint32_t ab = sb + EASH + buf * 10240 + aOff;
        const uint32_t bb = sb + EBSH + buf * 10240 + bOff;
#pragma unroll
        for (int ks = 0; ks < 2; ks++) {
            const uint32_t ko = ks * 32;   // 16 halves = 32 bytes
            uint32_t bfr[8];
            ldm4(&bfr[0], bb + ko);           // nt0.b0, nt0.b1, nt1.b0, nt1.b1
            ldm4(&bfr[4], bb + 1280 + ko);    // nt2, nt3
            uint32_t afr[4];
            ldm4(afr, ab + ko);               // mt=0
            mma16(acc[0][0], afr, &bfr[0]);
            mma16(acc[0][1], afr, &bfr[2]);
            mma16(acc[0][2], afr, &bfr[4]);
            mma16(acc[0][3], afr, &bfr[6]);
            ldm4(afr, ab + 1280 + ko);        // mt=1
            mma16(acc[1][0], afr, &bfr[0]);
            mma16(acc[1][1], afr, &bfr[2]);
            mma16(acc[1][2], afr, &bfr[4]);
            mma16(acc[1][3], afr, &bfr[6]);
        }
    };

    // ---- prologue ----
    ldgA(0);
    stageB(0, 0);                 // g0 = B0
    stsA(0);                      // waits LDG0
    ldgA(1);

    // chunk 0
    cp_wait0();                   // B0
    __syncthreads();              // publishes A0 STS + indices
    stageB(1, 1);                 // g1 = B1
    {   // xl/xr gathers into smem (g2); 256 rows x 272B
#pragma unroll
        for (int j = 0; j < 8; j++) {
            int s = tid + 512 * j;
            int row = s >> 4, u = s & 15;
            int idx = row & 127;
            const __half* gp = (j < 4)
                ? g_xlh + (size_t)src_s[idx] * 128 + u * 8
                : g_xrh + (size_t)dst_s[idx] * 128 + u * 8;
            cp16(sb + EGATH + row * 272 + u * 16, gp, 16);
        }
        cp_commit();              // g2 = EPI
    }
    compute(0);
    stsA(1); ldgA(2);

    // chunk 1
    cp_wait1();                   // B1 done (EPI may pend)
    __syncthreads();
    stageB(2, 0);                 // g3 = B2
    compute(1);
    stsA(0); ldgA(3);

    // chunk 2
    cp_wait0();                   // B2 + EPI done
    __syncthreads();              // publishes gather buffer
    stageB(3, 1);                 // g4 = B3
    compute(0);
    stsA(1);

    // chunk 3
    cp_wait0();                   // B3
    __syncthreads();
    compute(1);

    // ---- epilogue: conflict-free LDS of staged xl/xr; head = wn ----
#pragma unroll
    for (int mt = 0; mt < 2; mt++) {
#pragma unroll
        for (int half = 0; half < 2; half++) {
            int row = wm * 32 + mt * 16 + half * 8 + grp;
            const __half* xl = gath + (size_t)row * GSTR;
            const __half* xr = gath + (size_t)(128 + row) * GSTR;
            float partial = 0.f;
#pragma unroll
            for (int nt = 0; nt < 4; nt++) {
                int col = wn * 32 + nt * 8 + tg * 2;
                float2 a = __half22float2(*(const __half2*)(xl + col));
                float2 b = __half22float2(*(const __half2*)(xr + col));
                float z0 = acc[mt][nt][half * 2 + 0] + a.x + b.x;
                float z1 = acc[mt][nt][half * 2 + 1] + a.y + b.y;
                z0 = (z0 > 0.f) ? z0 : 0.2f * z0;
                z1 = (z1 > 0.f) ? z1 : 0.2f * z1;
                partial += z0 * att_s[col] + z1 * att_s[col + 1];
            }
            partial += __shfl_xor_sync(0xFFFFFFFFu, partial, 1);
            partial += __shfl_xor_sync(0xFFFFFFFFu, partial, 2);
            if (tg == 0)
                g_logits[(size_t)(e0 + row) * 4 + wn] = partial;
        }
    }
}

// ---------------- CSR build ----------------
__global__ void count_kernel(const int* __restrict__ dst) {
    int e = blockIdx.x * blockDim.x + threadIdx.x;
    if (e < ENUM) atomicAdd(&g_cnt[dst[e]], 1);
}

__global__ __launch_bounds__(1024) void scan_kernel() {
    __shared__ int part[1024];
    const int t = threadIdx.x;
    const int CH = (NLR + 1023) / 1024;
    int start = t * CH, end = min(start + CH, NLR);
    int s = 0;
    for (int i = start; i < end; i++) s += g_cnt[i];
    part[t] = s;
    __syncthreads();
    for (int off = 1; off < 1024; off <<= 1) {
        int v = (t >= off) ? part[t - off] : 0;
        __syncthreads();
        part[t] += v;
        __syncthreads();
    }
    int run = part[t] - s;
    for (int i = start; i < end; i++) {
        g_off[i] = run; g_cur[i] = run;
        run += g_cnt[i];
    }
    if (t == 1023) g_off[NLR] = part[1023];
}

__global__ void fill_kernel(const int* __restrict__ dst) {
    int e = blockIdx.x * blockDim.x + threadIdx.x;
    if (e < ENUM) {
        int p = atomicAdd(&g_cur[dst[e]], 1);
        g_elist[p] = e;
    }
}

// =================================================================
// Warp-per-node fused segment softmax + message + b_conv + LayerNorm.
// =================================================================
__global__ __launch_bounds__(256) void message_ln_kernel(
    const int* __restrict__ src,
    const float* __restrict__ bconv,
    const float* __restrict__ lng, const float* __restrict__ lnb)
{
    const int node = (blockIdx.x * blockDim.x + threadIdx.x) >> 5;
    const int lane = threadIdx.x & 31;
    if (node >= NLR) return;

    const int h  = lane >> 3;
    const int c4 = lane * 4;
    const int off0 = g_off[node];
    const int deg  = g_off[node + 1] - off0;

    float4 mx = make_float4(-1e30f, -1e30f, -1e30f, -1e30f);
    for (int i = lane; i < deg; i += 32) {
        int e = __ldg(&g_elist[off0 + i]);
        float4 lg = *(const float4*)&g_logits[(size_t)e * 4];
        mx.x = fmaxf(mx.x, lg.x); mx.y = fmaxf(mx.y, lg.y);
        mx.z = fmaxf(mx.z, lg.z); mx.w = fmaxf(mx.w, lg.w);
    }
#pragma unroll
    for (int o = 16; o; o >>= 1) {
        mx.x = fmaxf(mx.x, __shfl_xor_sync(0xFFFFFFFFu, mx.x, o));
        mx.y = fmaxf(mx.y, __shfl_xor_sync(0xFFFFFFFFu, mx.y, o));
        mx.z = fmaxf(mx.z, __shfl_xor_sync(0xFFFFFFFFu, mx.z, o));
        mx.w = fmaxf(mx.w, __shfl_xor_sync(0xFFFFFFFFu, mx.w, o));
    }

    float4 sm = make_float4(0.f, 0.f, 0.f, 0.f);
    for (int i = lane; i < deg; i += 32) {
        int e = __ldg(&g_elist[off0 + i]);
        float4 lg = *(const float4*)&g_logits[(size_t)e * 4];
        sm.x += __expf(lg.x - mx.x); sm.y += __expf(lg.y - mx.y);
        sm.z += __expf(lg.z - mx.z); sm.w += __expf(lg.w - mx.w);
    }
#pragma unroll
    for (int o = 16; o; o >>= 1) {
        sm.x += __shfl_xor_sync(0xFFFFFFFFu, sm.x, o);
        sm.y += __shfl_xor_sync(0xFFFFFFFFu, sm.y, o);
        sm.z += __shfl_xor_sync(0xFFFFFFFFu, sm.z, o);
        sm.w += __shfl_xor_sync(0xFFFFFFFFu, sm.w, o);
    }

    const float m_h = (h == 0) ? mx.x : (h == 1) ? mx.y : (h == 2) ? mx.z : mx.w;
    const float s_h = (h == 0) ? sm.x : (h == 1) ? sm.y : (h == 2) ? sm.z : sm.w;
    const float inv_h = 1.f / (s_h + 1e-16f);

    float4 acc = make_float4(0.f, 0.f, 0.f, 0.f);
    for (int j = 0; j < deg; j++) {
        int e  = __ldg(&g_elist[off0 + j]);
        int sr = __ldg(&src[e]);
        float a = __expf(__ldg(&g_logits[(size_t)e * 4 + h]) - m_h);
        const __half2* xp = (const __half2*)(g_xlh + (size_t)sr * 128 + c4);
        float2 x01 = __half22float2(xp[0]);
        float2 x23 = __half22float2(xp[1]);
        acc.x = fmaf(a, x01.x, acc.x); acc.y = fmaf(a, x01.y, acc.y);
        acc.z = fmaf(a, x23.x, acc.z); acc.w = fmaf(a, x23.y, acc.w);
    }
    float4 bc = *(const float4*)&bconv[c4];
    float4 msg;
    msg.x = acc.x * inv_h + bc.x; msg.y = acc.y * inv_h + bc.y;
    msg.z = acc.z * inv_h + bc.z; msg.w = acc.w * inv_h + bc.w;

    float s1 = msg.x + msg.y + msg.z + msg.w;
    float s2 = msg.x * msg.x + msg.y * msg.y + msg.z * msg.z + msg.w * msg.w;
#pragma unroll
    for (int o = 16; o; o >>= 1) {
        s1 += __shfl_xor_sync(0xFFFFFFFFu, s1, o);
        s2 += __shfl_xor_sync(0xFFFFFFFFu, s2, o);
    }
    float mu  = s1 * (1.f / 128.f);
    float var = fmaxf(s2 * (1.f / 128.f) - mu * mu, 0.f);
    float r = rsqrtf(var + 1e-5f);

    float4 g = *(const float4*)&lng[c4];
    float4 b = *(const float4*)&lnb[c4];
    float4 o4;
    o4.x = (msg.x - mu) * r * g.x + b.x;
    o4.y = (msg.y - mu) * r * g.y + b.y;
    o4.z = (msg.z - mu) * r * g.z + b.z;
    o4.w = (msg.w - mu) * r * g.w + b.w;
    *(float4*)&g_ln[(size_t)node * 128 + c4] = o4;
}

// =================================================================
extern "C" void kernel_launch(void* const* d_in, const int* in_sizes, int n_in,
                              void* d_out, int out_size) {
    const float* left  = (const float*)d_in[0];
    const int*   eidx  = (const int*)d_in[1];
    const float* ef    = (const float*)d_in[2];
    const float* right = (const float*)d_in[3];
    const float* W_l   = (const float*)d_in[4];
    const float* b_l   = (const float*)d_in[5];
    const float* W_r   = (const float*)d_in[6];
    const float* b_r   = (const float*)d_in[7];
    const float* W_e   = (const float*)d_in[8];
    const float* att   = (const float*)d_in[9];
    const float* bconv = (const float*)d_in[10];
    const float* ln_g  = (const float*)d_in[11];
    const float* ln_b  = (const float*)d_in[12];
    const float* W1    = (const float*)d_in[13];
    const float* b1    = (const float*)d_in[14];
    const float* W2    = (const float*)d_in[15];
    const float* b2    = (const float*)d_in[16];
    float* out = (float*)d_out;

    const int* src = eidx;
    const int* dst = eidx + ENUM;

    float*  ln;  cudaGetSymbolAddress((void**)&ln,  g_ln);
    float*  h1;  cudaGetSymbolAddress((void**)&h1,  g_h1);
    __half* wTh; cudaGetSymbolAddress((void**)&wTh, g_wTh);
    int*    cnt; cudaGetSymbolAddress((void**)&cnt, g_cnt);

    cudaFuncSetAttribute(gemm128,
                         cudaFuncAttributeMaxDynamicSharedMemorySize, SMEM_GEMM);
    cudaFuncSetAttribute(gemm_dual,
                         cudaFuncAttributeMaxDynamicSharedMemorySize, SMEM_GEMM);
    cudaFuncSetAttribute(edge_logits_kernel,
                         cudaFuncAttributeMaxDynamicSharedMemorySize, SMEM_EDGE2);

    const int gblk = (NLR + 127) / 128;   // 391

    // side stream for the CSR branch (independent of the GEMM chain)
    cudaStream_t s2;
    cudaStreamCreateWithFlags(&s2, cudaStreamNonBlocking);
    cudaEvent_t evFork, evJoin;
    cudaEventCreateWithFlags(&evFork, cudaEventDisableTiming);
    cudaEventCreateWithFlags(&evJoin, cudaEventDisableTiming);

    cudaEventRecord(evFork, 0);
    cudaStreamWaitEvent(s2, evFork, 0);

    cudaMemsetAsync(cnt, 0, NLR * sizeof(int), s2);

    transpose5<<<96, dim3(32, 8)>>>(W_l, W_r, W_e, W1, W2);                  // k1
    count_kernel<<<(ENUM + 255) / 256, 256, 0, s2>>>(dst);                   // k2
    gemm_dual<<<2 * gblk, 512, SMEM_GEMM>>>(left, wTh + WL_T, b_l,
                                            right, wTh + WR_T, b_r,
                                            NLR, gblk);                      // k3
    edge_logits_kernel<<<ENUM / 128, 512, SMEM_EDGE2>>>(ef, wTh + WE_T,
                                                        src, dst, att);      // k4 (profiled)
    scan_kernel<<<1, 1024, 0, s2>>>();                                       // k5
    fill_kernel<<<(ENUM + 255) / 256, 256, 0, s2>>>(dst);                    // k6

    cudaEventRecord(evJoin, s2);
    cudaStreamWaitEvent(0, evJoin, 0);

    message_ln_kernel<<<(NLR * 32 + 255) / 256, 256>>>(src, bconv, ln_g, ln_b); // k7
    gemm128<<<gblk, 512, SMEM_GEMM>>>(ln, 128, right, 128, wTh + W1_T, 256,
                                      b1, h1, NLR, 1);                       // k8
    gemm128<<<gblk, 512, SMEM_GEMM>>>(h1, 128, nullptr, 0, wTh + W2_T, 128,
                                      b2, out, NLR, 0);                      // k9
}

// round 13
// speedup vs baseline: 1.8412x; 1.0708x over previous
#include <cuda_runtime.h>
#include <cuda_fp16.h>
#include <math.h>
#include <stdint.h>

#define NLR  50000
#define EMBD 128
#define ENUM 800000

// ---------------- device scratch (no allocations allowed) ----------------
__device__ float  g_logits[(size_t)ENUM * 4];
__device__ __half g_xlh[(size_t)NLR * EMBD];
__device__ __half g_xrh[(size_t)NLR * EMBD];
__device__ float  g_ln[(size_t)NLR * EMBD];
__device__ float  g_h1[(size_t)NLR * EMBD];
__device__ __half g_wTh[128 * 768];          // wlT|wrT|weT|w1T(128x256)|w2T
__device__ int    g_cnt[NLR];
__device__ int    g_off[NLR + 1];
__device__ int    g_cur[NLR];
__device__ int    g_elist[ENUM];

#define WL_T 0
#define WR_T 16384
#define WE_T 32768
#define W1_T 49152
#define W2_T 81920

// ---------------- helpers ----------------
__device__ __forceinline__ void mma16(float c[4], const uint32_t a[4], const uint32_t b[2]) {
    asm volatile(
        "mma.sync.aligned.m16n8k16.row.col.f32.f16.f16.f32 "
        "{%0,%1,%2,%3},{%4,%5,%6,%7},{%8,%9},{%0,%1,%2,%3};\n"
        : "+f"(c[0]), "+f"(c[1]), "+f"(c[2]), "+f"(c[3])
        : "r"(a[0]), "r"(a[1]), "r"(a[2]), "r"(a[3]), "r"(b[0]), "r"(b[1]));
}
__device__ __forceinline__ void ldm4(uint32_t* r, uint32_t addr) {
    asm volatile("ldmatrix.sync.aligned.m8n8.x4.shared.b16 {%0,%1,%2,%3}, [%4];"
                 : "=r"(r[0]), "=r"(r[1]), "=r"(r[2]), "=r"(r[3]) : "r"(addr));
}
__device__ __forceinline__ void cp16(uint32_t saddr, const void* gptr, int sz) {
    asm volatile("cp.async.cg.shared.global [%0], [%1], 16, %2;\n"
                 :: "r"(saddr), "l"(gptr), "r"(sz));
}
__device__ __forceinline__ void cp_commit() { asm volatile("cp.async.commit_group;\n"); }
__device__ __forceinline__ void cp_wait1()  { asm volatile("cp.async.wait_group 1;\n"); }
__device__ __forceinline__ void cp_wait0()  { asm volatile("cp.async.wait_group 0;\n"); }
__device__ __forceinline__ uint32_t sa(const void* p) {
    return (uint32_t)__cvta_generic_to_shared(p);
}
__device__ __forceinline__ float4 ldcs4(const float* p) {
    return __ldcs((const float4*)p);
}

// ---- GEMM smem layout: A 2x10240, B 2x10240, bias ----
#define GA_OFF 0
#define GB_OFF 20480
#define GBIAS  40960
#define SMEM_GEMM (GBIAS + 512)

// ---- edge kernel smem layout ----
#define EASH  0                     // 2 x 128 x 80B   (20480 B)
#define EBSH  20480                 // 2 x 128 x 80B   (20480 B)
#define EGATH 40960                 // 256 rows x 272B (69632 B)
#define EATT  110592                // 128 floats
#define ESRC  111104                // 128 ints
#define EDST  111616                // 128 ints
#define SMEM_EDGE2 112128
#define GSTR  136                   // gather row stride in halves (272 B)

// =================================================================
// one-time weight transpose + fp16 convert: g_wTh[n][k] = h(W[k][n])
// =================================================================
__global__ void transpose5(const float* __restrict__ Wl, const float* __restrict__ Wr,
                           const float* __restrict__ We, const float* __restrict__ W1,
                           const float* __restrict__ W2) {
    __shared__ float t[32][33];
    int b = blockIdx.x;
    const float* W; __half* out; int K;
    if      (b < 16) { W = Wl; out = g_wTh + WL_T; K = 128; }
    else if (b < 32) { W = Wr; out = g_wTh + WR_T; K = 128; b -= 16; }
    else if (b < 48) { W = We; out = g_wTh + WE_T; K = 128; b -= 32; }
    else if (b < 80) { W = W1; out = g_wTh + W1_T; K = 256; b -= 48; }
    else             { W = W2; out = g_wTh + W2_T; K = 128; b -= 80; }
    const int ktiles = K >> 5;
    const int k0 = (b % ktiles) * 32, n0 = (b / ktiles) * 32;
    const int tx = threadIdx.x, ty = threadIdx.y;
#pragma unroll
    for (int i = 0; i < 4; i++)
        t[ty + 8 * i][tx] = W[(size_t)(k0 + ty + 8 * i) * 128 + n0 + tx];
    __syncthreads();
#pragma unroll
    for (int i = 0; i < 4; i++)
        out[(size_t)(n0 + ty + 8 * i) * K + k0 + tx] = __float2half(t[tx][ty + 8 * i]);
}

// =================================================================
// GEMM body v13: ldmatrix fragments, single sync per chunk.
// C[M,128] = act( [A1|A2](M, K1+K2) @ BT^T + bias ), BT fp16 [128][Kb].
// 512 threads, 4x4 warp grid, 32x32 warp tiles.
// =================================================================
template <bool HALF_OUT>
__device__ __forceinline__ void gemm_body(
    const float* __restrict__ A1, int K1,
    const float* __restrict__ A2, int K2,
    const __half* __restrict__ BT, int Kb,
    const float* __restrict__ bias, float* __restrict__ C, __half* __restrict__ Ch,
    int M, int doRelu, int m0, char* smem_raw)
{
    const uint32_t sb = sa(smem_raw);
    float* bias_s = (float*)(smem_raw + GBIAS);

    const int tid = threadIdx.x;
    if (tid < 128) bias_s[tid] = bias[tid];

    const int warp = tid >> 5, lane = tid & 31;
    const int wm = warp & 3, wn = warp >> 2;
    const int grp = lane >> 2, tg = lane & 3;

    const int nch1 = K1 >> 5;
    const int nch  = Kb >> 5;

    const int ar0 = tid >> 3, ac = (tid & 7) * 4;
    float4 a0, a1;

    auto ldgA = [&](int c) {
        const float* A; int K, ka;
        if (c < nch1) { A = A1; K = K1; ka = c * 32; }
        else          { A = A2; K = K2; ka = c * 32 - K1; }
        int g0 = m0 + ar0, g1 = m0 + ar0 + 64;
        a0 = (g0 < M) ? *(const float4*)(A + (size_t)g0 * K + ka + ac)
                      : make_float4(0.f, 0.f, 0.f, 0.f);
        a1 = (g1 < M) ? *(const float4*)(A + (size_t)g1 * K + ka + ac)
                      : make_float4(0.f, 0.f, 0.f, 0.f);
    };
    auto stsA = [&](int buf) {
        char* base = smem_raw + GA_OFF + buf * 10240;
        __half2 h0 = __floats2half2_rn(a0.x, a0.y), h1 = __floats2half2_rn(a0.z, a0.w);
        *(uint2*)(base + ar0 * 80 + ac * 2) = make_uint2(*(uint32_t*)&h0, *(uint32_t*)&h1);
        __half2 h2 = __floats2half2_rn(a1.x, a1.y), h3 = __floats2half2_rn(a1.z, a1.w);
        *(uint2*)(base + (ar0 + 64) * 80 + ac * 2) = make_uint2(*(uint32_t*)&h2, *(uint32_t*)&h3);
    };
    const int br = tid >> 2, bu = (tid & 3) * 8;
    auto stageB = [&](int c, int buf) {
        cp16(sb + GB_OFF + buf * 10240 + br * 80 + bu * 2,
             BT + (size_t)br * Kb + c * 32 + bu, 16);
        cp_commit();
    };

    const uint32_t aOff = (uint32_t)(wm * 32 + (lane & 15)) * 80 + (uint32_t)((lane >> 4) << 3) * 2;
    const uint32_t bOff = (uint32_t)(wn * 32 + (lane & 7) + ((lane >> 4) << 3)) * 80
                        + (uint32_t)(((lane >> 3) & 1) << 3) * 2;

    float acc[2][4][4];
#pragma unroll
    for (int a = 0; a < 2; a++)
#pragma unroll
        for (int b = 0; b < 4; b++)
#pragma unroll
            for (int k = 0; k < 4; k++) acc[a][b][k] = 0.f;

    auto compute = [&](int buf) {
        const uint32_t ab = sb + GA_OFF + buf * 10240 + aOff;
        const uint32_t bb = sb + GB_OFF + buf * 10240 + bOff;
#pragma unroll
        for (int ks = 0; ks < 2; ks++) {
            const uint32_t ko = ks * 32;
            uint32_t bfr[8];
            ldm4(&bfr[0], bb + ko);
            ldm4(&bfr[4], bb + 1280 + ko);
            uint32_t afr[4];
            ldm4(afr, ab + ko);
            mma16(acc[0][0], afr, &bfr[0]);
            mma16(acc[0][1], afr, &bfr[2]);
            mma16(acc[0][2], afr, &bfr[4]);
            mma16(acc[0][3], afr, &bfr[6]);
            ldm4(afr, ab + 1280 + ko);
            mma16(acc[1][0], afr, &bfr[0]);
            mma16(acc[1][1], afr, &bfr[2]);
            mma16(acc[1][2], afr, &bfr[4]);
            mma16(acc[1][3], afr, &bfr[6]);
        }
    };

    // prologue
    ldgA(0);
    stageB(0, 0);
    stsA(0);
    if (nch > 1) ldgA(1);

    for (int c = 0; c < nch; c++) {
        const int buf = c & 1;
        cp_wait0();
        __syncthreads();
        if (c + 1 < nch) stageB(c + 1, buf ^ 1);
        compute(buf);
        if (c + 1 < nch) {
            stsA(buf ^ 1);
            if (c + 2 < nch) ldgA(c + 2);
        }
    }

#pragma unroll
    for (int mt = 0; mt < 2; mt++) {
#pragma unroll
        for (int half = 0; half < 2; half++) {
            int grow = m0 + wm * 32 + mt * 16 + half * 8 + grp;
            if (grow < M) {
#pragma unroll
                for (int nt = 0; nt < 4; nt++) {
                    int cc = wn * 32 + nt * 8 + tg * 2;
                    float v0 = acc[mt][nt][half * 2 + 0] + bias_s[cc];
                    float v1 = acc[mt][nt][half * 2 + 1] + bias_s[cc + 1];
                    if (doRelu) { v0 = fmaxf(v0, 0.f); v1 = fmaxf(v1, 0.f); }
                    if (HALF_OUT) {
                        __half2 h = __floats2half2_rn(v0, v1);
                        *(__half2*)(Ch + (size_t)grow * 128 + cc) = h;
                    } else {
                        float2 o; o.x = v0; o.y = v1;
                        *(float2*)(C + (size_t)grow * 128 + cc) = o;
                    }
                }
            }
        }
    }
}

__global__ __launch_bounds__(512, 2) void gemm128(
    const float* __restrict__ A1, int K1,
    const float* __restrict__ A2, int K2,
    const __half* __restrict__ BT, int Kb,
    const float* __restrict__ bias, float* __restrict__ C, int M, int doRelu)
{
    extern __shared__ char smem_raw[];
    gemm_body<false>(A1, K1, A2, K2, BT, Kb, bias, C, nullptr, M, doRelu,
                     blockIdx.x * 128, smem_raw);
}

__global__ __launch_bounds__(512, 2) void gemm_dual(
    const float* __restrict__ Aa, const __half* __restrict__ BTa,
    const float* __restrict__ ba,
    const float* __restrict__ Ab, const __half* __restrict__ BTb,
    const float* __restrict__ bb,
    int M, int half)
{
    extern __shared__ char smem_raw[];
    if (blockIdx.x < half)
        gemm_body<true>(Aa, 128, nullptr, 0, BTa, 128, ba, nullptr, g_xlh, M, 0,
                        blockIdx.x * 128, smem_raw);
    else
        gemm_body<true>(Ab, 128, nullptr, 0, BTb, 128, bb, nullptr, g_xrh, M, 0,
                        (blockIdx.x - half) * 128, smem_raw);
}

// =================================================================
// Edge kernel v13: ldmatrix fragments, single sync/chunk, cp.async
// smem-staged xl/xr gathers, __ldcs streaming EF loads.
// =================================================================
__global__ __launch_bounds__(512, 2) void edge_logits_kernel(
    const float* __restrict__ EF, const __half* __restrict__ WeT,
    const int* __restrict__ src, const int* __restrict__ dst,
    const float* __restrict__ att)
{
    extern __shared__ char smem[];
    const uint32_t sb = sa(smem);
    float* att_s = (float*)(smem + EATT);
    int*   src_s = (int*)(smem + ESRC);
    int*   dst_s = (int*)(smem + EDST);
    const __half* gath = (const __half*)(smem + EGATH);

    const int tid = threadIdx.x;
    const int e0  = blockIdx.x * 128;
    const int warp = tid >> 5, lane = tid & 31;
    const int wm = warp & 3, wn = warp >> 2;
    const int grp = lane >> 2, tg = lane & 3;

    if (tid < 128) {
        src_s[tid] = src[e0 + tid];
        dst_s[tid] = dst[e0 + tid];
        att_s[tid] = att[tid];
    }

    const int ar0 = tid >> 3, ac = (tid & 7) * 4;
    float4 a0, a1;
    auto ldgA = [&](int c) {
        const int ka = c * 32;
        a0 = ldcs4(EF + (size_t)(e0 + ar0) * 128 + ka + ac);
        a1 = ldcs4(EF + (size_t)(e0 + ar0 + 64) * 128 + ka + ac);
    };
    auto stsA = [&](int buf) {
        char* base = smem + EASH + buf * 10240;
        __half2 h0 = __floats2half2_rn(a0.x, a0.y), h1 = __floats2half2_rn(a0.z, a0.w);
        *(uint2*)(base + ar0 * 80 + ac * 2) = make_uint2(*(uint32_t*)&h0, *(uint32_t*)&h1);
        __half2 h2 = __floats2half2_rn(a1.x, a1.y), h3 = __floats2half2_rn(a1.z, a1.w);
        *(uint2*)(base + (ar0 + 64) * 80 + ac * 2) = make_uint2(*(uint32_t*)&h2, *(uint32_t*)&h3);
    };
    const int br = tid >> 2, bu = (tid & 3) * 8;
    auto stageB = [&](int c, int buf) {
        cp16(sb + EBSH + buf * 10240 + br * 80 + bu * 2,
             WeT + (size_t)br * 128 + c * 32 + bu, 16);
        cp_commit();
    };

    const uint32_t aOff = (uint32_t)(wm * 32 + (lane & 15)) * 80 + (uint32_t)((lane >> 4) << 3) * 2;
    const uint32_t bOff = (uint32_t)(wn * 32 + (lane & 7) + ((lane >> 4) << 3)) * 80
                        + (uint32_t)(((lane >> 3) & 1) << 3) * 2;

    float acc[2][4][4];
#pragma unroll
    for (int a = 0; a < 2; a++)
#pragma unroll
        for (int b = 0; b < 4; b++)
#pragma unroll
            for (int k = 0; k < 4; k++) acc[a][b][k] = 0.f;

    auto compute = [&](int buf) {
        const uint32_t ab = sb + EASH + buf * 10240 + aOff;
        const uint32_t bb = sb + EBSH + buf * 10240 + bOff;
#pragma unroll
        for (int ks = 0; ks < 2; ks++) {
            const uint32_t ko = ks * 32;
            uint32_t bfr[8];
            ldm4(&bfr[0], bb + ko);
            ldm4(&bfr[4], bb + 1280 + ko);
            uint32_t afr[4];
            ldm4(afr, ab + ko);
            mma16(acc[0][0], afr, &bfr[0]);
            mma16(acc[0][1], afr, &bfr[2]);
            mma16(acc[0][2], afr, &bfr[4]);
            mma16(acc[0][3], afr, &bfr[6]);
            ldm4(afr, ab + 1280 + ko);
            mma16(acc[1][0], afr, &bfr[0]);
            mma16(acc[1][1], afr, &bfr[2]);
            mma16(acc[1][2], afr, &bfr[4]);
            mma16(acc[1][3], afr, &bfr[6]);
        }
    };

    // ---- prologue ----
    ldgA(0);
    stageB(0, 0);                 // g0 = B0
    stsA(0);
    ldgA(1);

    // chunk 0
    cp_wait0();                   // B0
    __syncthreads();              // publishes A0 STS + indices
    stageB(1, 1);                 // g1 = B1
    {   // xl/xr gathers into smem (g2); 256 rows x 272B
#pragma unroll
        for (int j = 0; j < 8; j++) {
            int s = tid + 512 * j;
            int row = s >> 4, u = s & 15;
            int idx = row & 127;
            const __half* gp = (j < 4)
                ? g_xlh + (size_t)src_s[idx] * 128 + u * 8
                : g_xrh + (size_t)dst_s[idx] * 128 + u * 8;
            cp16(sb + EGATH + row * 272 + u * 16, gp, 16);
        }
        cp_commit();              // g2 = EPI
    }
    compute(0);
    stsA(1); ldgA(2);

    // chunk 1
    cp_wait1();                   // B1 done (EPI may pend)
    __syncthreads();
    stageB(2, 0);                 // g3 = B2
    compute(1);
    stsA(0); ldgA(3);

    // chunk 2
    cp_wait0();                   // B2 + EPI done
    __syncthreads();              // publishes gather buffer
    stageB(3, 1);                 // g4 = B3
    compute(0);
    stsA(1);

    // chunk 3
    cp_wait0();                   // B3
    __syncthreads();
    compute(1);

    // ---- epilogue: conflict-free LDS of staged xl/xr; head = wn ----
#pragma unroll
    for (int mt = 0; mt < 2; mt++) {
#pragma unroll
        for (int half = 0; half < 2; half++) {
            int row = wm * 32 + mt * 16 + half * 8 + grp;
            const __half* xl = gath + (size_t)row * GSTR;
            const __half* xr = gath + (size_t)(128 + row) * GSTR;
            float partial = 0.f;
#pragma unroll
            for (int nt = 0; nt < 4; nt++) {
                int col = wn * 32 + nt * 8 + tg * 2;
                float2 a = __half22float2(*(const __half2*)(xl + col));
                float2 b = __half22float2(*(const __half2*)(xr + col));
                float z0 = acc[mt][nt][half * 2 + 0] + a.x + b.x;
                float z1 = acc[mt][nt][half * 2 + 1] + a.y + b.y;
                z0 = (z0 > 0.f) ? z0 : 0.2f * z0;
                z1 = (z1 > 0.f) ? z1 : 0.2f * z1;
                partial += z0 * att_s[col] + z1 * att_s[col + 1];
            }
            partial += __shfl_xor_sync(0xFFFFFFFFu, partial, 1);
            partial += __shfl_xor_sync(0xFFFFFFFFu, partial, 2);
            if (tg == 0)
                g_logits[(size_t)(e0 + row) * 4 + wn] = partial;
        }
    }
}

// ---------------- CSR build ----------------
__global__ void count_kernel(const int* __restrict__ dst) {
    int e = blockIdx.x * blockDim.x + threadIdx.x;
    if (e < ENUM) atomicAdd(&g_cnt[dst[e]], 1);
}

__global__ __launch_bounds__(1024) void scan_kernel() {
    __shared__ int part[1024];
    const int t = threadIdx.x;
    const int CH = (NLR + 1023) / 1024;
    int start = t * CH, end = min(start + CH, NLR);
    int s = 0;
    for (int i = start; i < end; i++) s += g_cnt[i];
    part[t] = s;
    __syncthreads();
    for (int off = 1; off < 1024; off <<= 1) {
        int v = (t >= off) ? part[t - off] : 0;
        __syncthreads();
        part[t] += v;
        __syncthreads();
    }
    int run = part[t] - s;
    for (int i = start; i < end; i++) {
        g_off[i] = run; g_cur[i] = run;
        run += g_cnt[i];
    }
    if (t == 1023) g_off[NLR] = part[1023];
}

__global__ void fill_kernel(const int* __restrict__ dst) {
    int e = blockIdx.x * blockDim.x + threadIdx.x;
    if (e < ENUM) {
        int p = atomicAdd(&g_cur[dst[e]], 1);
        g_elist[p] = e;
    }
}

// =================================================================
// Warp-per-node fused segment softmax + message + b_conv + LayerNorm.
// =================================================================
__global__ __launch_bounds__(256) void message_ln_kernel(
    const int* __restrict__ src,
    const float* __restrict__ bconv,
    const float* __restrict__ lng, const float* __restrict__ lnb)
{
    const int node = (blockIdx.x * blockDim.x + threadIdx.x) >> 5;
    const int lane = threadIdx.x & 31;
    if (node >= NLR) return;

    const int h  = lane >> 3;
    const int c4 = lane * 4;
    const int off0 = g_off[node];
    const int deg  = g_off[node + 1] - off0;

    float4 mx = make_float4(-1e30f, -1e30f, -1e30f, -1e30f);
    for (int i = lane; i < deg; i += 32) {
        int e = __ldg(&g_elist[off0 + i]);
        float4 lg = *(const float4*)&g_logits[(size_t)e * 4];
        mx.x = fmaxf(mx.x, lg.x); mx.y = fmaxf(mx.y, lg.y);
        mx.z = fmaxf(mx.z, lg.z); mx.w = fmaxf(mx.w, lg.w);
    }
#pragma unroll
    for (int o = 16; o; o >>= 1) {
        mx.x = fmaxf(mx.x, __shfl_xor_sync(0xFFFFFFFFu, mx.x, o));
        mx.y = fmaxf(mx.y, __shfl_xor_sync(0xFFFFFFFFu, mx.y, o));
        mx.z = fmaxf(mx.z, __shfl_xor_sync(0xFFFFFFFFu, mx.z, o));
        mx.w = fmaxf(mx.w, __shfl_xor_sync(0xFFFFFFFFu, mx.w, o));
    }

    float4 sm = make_float4(0.f, 0.f, 0.f, 0.f);
    for (int i = lane; i < deg; i += 32) {
        int e = __ldg(&g_elist[off0 + i]);
        float4 lg = *(const float4*)&g_logits[(size_t)e * 4];
        sm.x += __expf(lg.x - mx.x); sm.y += __expf(lg.y - mx.y);
        sm.z += __expf(lg.z - mx.z); sm.w += __expf(lg.w - mx.w);
    }
#pragma unroll
    for (int o = 16; o; o >>= 1) {
        sm.x += __shfl_xor_sync(0xFFFFFFFFu, sm.x, o);
        sm.y += __shfl_xor_sync(0xFFFFFFFFu, sm.y, o);
        sm.z += __shfl_xor_sync(0xFFFFFFFFu, sm.z, o);
        sm.w += __shfl_xor_sync(0xFFFFFFFFu, sm.w, o);
    }

    const float m_h = (h == 0) ? mx.x : (h == 1) ? mx.y : (h == 2) ? mx.z : mx.w;
    const float s_h = (h == 0) ? sm.x : (h == 1) ? sm.y : (h == 2) ? sm.z : sm.w;
    const float inv_h = 1.f / (s_h + 1e-16f);

    float4 acc = make_float4(0.f, 0.f, 0.f, 0.f);
    for (int j = 0; j < deg; j++) {
        int e  = __ldg(&g_elist[off0 + j]);
        int sr = __ldg(&src[e]);
        float a = __expf(__ldg(&g_logits[(size_t)e * 4 + h]) - m_h);
        const __half2* xp = (const __half2*)(g_xlh + (size_t)sr * 128 + c4);
        float2 x01 = __half22float2(xp[0]);
        float2 x23 = __half22float2(xp[1]);
        acc.x = fmaf(a, x01.x, acc.x); acc.y = fmaf(a, x01.y, acc.y);
        acc.z = fmaf(a, x23.x, acc.z); acc.w = fmaf(a, x23.y, acc.w);
    }
    float4 bc = *(const float4*)&bconv[c4];
    float4 msg;
    msg.x = acc.x * inv_h + bc.x; msg.y = acc.y * inv_h + bc.y;
    msg.z = acc.z * inv_h + bc.z; msg.w = acc.w * inv_h + bc.w;

    float s1 = msg.x + msg.y + msg.z + msg.w;
    float s2 = msg.x * msg.x + msg.y * msg.y + msg.z * msg.z + msg.w * msg.w;
#pragma unroll
    for (int o = 16; o; o >>= 1) {
        s1 += __shfl_xor_sync(0xFFFFFFFFu, s1, o);
        s2 += __shfl_xor_sync(0xFFFFFFFFu, s2, o);
    }
    float mu  = s1 * (1.f / 128.f);
    float var = fmaxf(s2 * (1.f / 128.f) - mu * mu, 0.f);
    float r = rsqrtf(var + 1e-5f);

    float4 g = *(const float4*)&lng[c4];
    float4 b = *(const float4*)&lnb[c4];
    float4 o4;
    o4.x = (msg.x - mu) * r * g.x + b.x;
    o4.y = (msg.y - mu) * r * g.y + b.y;
    o4.z = (msg.z - mu) * r * g.z + b.z;
    o4.w = (msg.w - mu) * r * g.w + b.w;
    *(float4*)&g_ln[(size_t)node * 128 + c4] = o4;
}

// =================================================================
extern "C" void kernel_launch(void* const* d_in, const int* in_sizes, int n_in,
                              void* d_out, int out_size) {
    const float* left  = (const float*)d_in[0];
    const int*   eidx  = (const int*)d_in[1];
    const float* ef    = (const float*)d_in[2];
    const float* right = (const float*)d_in[3];
    const float* W_l   = (const float*)d_in[4];
    const float* b_l   = (const float*)d_in[5];
    const float* W_r   = (const float*)d_in[6];
    const float* b_r   = (const float*)d_in[7];
    const float* W_e   = (const float*)d_in[8];
    const float* att   = (const float*)d_in[9];
    const float* bconv = (const float*)d_in[10];
    const float* ln_g  = (const float*)d_in[11];
    const float* ln_b  = (const float*)d_in[12];
    const float* W1    = (const float*)d_in[13];
    const float* b1    = (const float*)d_in[14];
    const float* W2    = (const float*)d_in[15];
    const float* b2    = (const float*)d_in[16];
    float* out = (float*)d_out;

    const int* src = eidx;
    const int* dst = eidx + ENUM;

    float*  ln;  cudaGetSymbolAddress((void**)&ln,  g_ln);
    float*  h1;  cudaGetSymbolAddress((void**)&h1,  g_h1);
    __half* wTh; cudaGetSymbolAddress((void**)&wTh, g_wTh);
    int*    cnt; cudaGetSymbolAddress((void**)&cnt, g_cnt);

    cudaFuncSetAttribute(gemm128,
                         cudaFuncAttributeMaxDynamicSharedMemorySize, SMEM_GEMM);
    cudaFuncSetAttribute(gemm_dual,
                         cudaFuncAttributeMaxDynamicSharedMemorySize, SMEM_GEMM);
    cudaFuncSetAttribute(edge_logits_kernel,
                         cudaFuncAttributeMaxDynamicSharedMemorySize, SMEM_EDGE2);

    const int gblk = (NLR + 127) / 128;   // 391

    // side stream for the CSR branch (independent of the GEMM chain)
    cudaStream_t s2;
    cudaStreamCreateWithFlags(&s2, cudaStreamNonBlocking);
    cudaEvent_t evFork, evJoin;
    cudaEventCreateWithFlags(&evFork, cudaEventDisableTiming);
    cudaEventCreateWithFlags(&evJoin, cudaEventDisableTiming);

    cudaEventRecord(evFork, 0);
    cudaStreamWaitEvent(s2, evFork, 0);

    cudaMemsetAsync(cnt, 0, NLR * sizeof(int), s2);

    transpose5<<<96, dim3(32, 8)>>>(W_l, W_r, W_e, W1, W2);                  // k1
    count_kernel<<<(ENUM + 255) / 256, 256, 0, s2>>>(dst);                   // k2
    gemm_dual<<<2 * gblk, 512, SMEM_GEMM>>>(left, wTh + WL_T, b_l,
                                            right, wTh + WR_T, b_r,
                                            NLR, gblk);                      // k3
    edge_logits_kernel<<<ENUM / 128, 512, SMEM_EDGE2>>>(ef, wTh + WE_T,
                                                        src, dst, att);      // k4 (profiled)
    scan_kernel<<<1, 1024, 0, s2>>>();                                       // k5
    fill_kernel<<<(ENUM + 255) / 256, 256, 0, s2>>>(dst);                    // k6

    cudaEventRecord(evJoin, s2);
    cudaStreamWaitEvent(0, evJoin, 0);

    message_ln_kernel<<<(NLR * 32 + 255) / 256, 256>>>(src, bconv, ln_g, ln_b); // k7
    gemm128<<<gblk, 512, SMEM_GEMM>>>(ln, 128, right, 128, wTh + W1_T, 256,
                                      b1, h1, NLR, 1);                       // k8
    gemm128<<<gblk, 512, SMEM_GEMM>>>(h1, 128, nullptr, 0, wTh + W2_T, 128,
                                      b2, out, NLR, 0);                      // k9
}